// round 1
// baseline (speedup 1.0000x reference)
#include <cuda_runtime.h>
#include <cstdint>

#define BTOT 8
#define CIN  384
#define HWSZ 4096
#define DDIM 128
#define NTOK 512
#define MROW (BTOT*HWSZ)   // 32768
#define KSEL 81
#define LN_EPS 1e-5f

// Output layout in d_out (float32): mask [8,1,64,64] | out_img [8,384,64,64] | results [8,8,81,512]
#define OUT_MASK 0
#define OUT_IMG  32768
#define OUT_RES  (32768 + BTOT*CIN*HWSZ)   // 12615680

// ---------------- scratch (device globals; no allocs allowed) ----------------
__device__ float g_dr_ln[NTOK*DDIM];      // ln(DR) rows [n][d]
__device__ float g_dr_rnorm[NTOK];        // 1/||ln(DR)[n]||
__device__ float g_xalign[(size_t)MROW*DDIM];
__device__ float g_ln2[(size_t)MROW*DDIM];   // ln(ln(sem(x)))
__device__ float g_cdlinv[MROW];             // 1/||ln(sem(x)) row||
__device__ float g_sim[(size_t)MROW*NTOK];   // softmax probs (64 MB)
__device__ float g_rowmax[MROW];             // max prob per row
__device__ float g_degrad[(size_t)MROW*DDIM];
__device__ int   g_topidx[BTOT*KSEL];

// ---------------- reduction helpers ----------------
__device__ __forceinline__ float wSum(float v){
    #pragma unroll
    for (int o=16;o;o>>=1) v += __shfl_xor_sync(0xFFFFFFFFu, v, o);
    return v;
}
__device__ __forceinline__ float wMax(float v){
    #pragma unroll
    for (int o=16;o;o>>=1) v = fmaxf(v, __shfl_xor_sync(0xFFFFFFFFu, v, o));
    return v;
}
__device__ __forceinline__ float blockSum128(float v, float* red){
    v = wSum(v);
    int w = threadIdx.x >> 5;
    if ((threadIdx.x & 31) == 0) red[w] = v;
    __syncthreads();
    float s = red[0] + red[1] + red[2] + red[3];
    __syncthreads();
    return s;
}

// ---------------- K1: layernorm of DR rows + column norms ----------------
__global__ void k_ln_dr(const float* __restrict__ DRp,
                        const float* __restrict__ w2, const float* __restrict__ b2){
    __shared__ float red[4];
    int n = blockIdx.x, t = threadIdx.x;   // 128 threads
    float v = DRp[n*DDIM + t];
    float mean = blockSum128(v, red) * (1.f/DDIM);
    float d = v - mean;
    float var = blockSum128(d*d, red) * (1.f/DDIM);
    float rstd = rsqrtf(var + LN_EPS);
    float ln = d * rstd * w2[t] + b2[t];
    g_dr_ln[n*DDIM + t] = ln;
    float ss = blockSum128(ln*ln, red);
    if (t == 0) g_dr_rnorm[n] = rsqrtf(ss);
}

// ---------------- K2: conv_in GEMM  x[b,c,l] * Win[d,c] -> x_align[m,d] ----------------
__global__ __launch_bounds__(256) void k_conv_in(const float* __restrict__ x,
                                                 const float* __restrict__ W,
                                                 const float* __restrict__ bias){
    __shared__ float As[16][64];   // [k][m]
    __shared__ float Bs[16][68];   // [k][d]  (pad 68 -> float4 aligned)
    int t = threadIdx.x;
    int l0 = blockIdx.x * 64, d0 = blockIdx.y * 64, b = blockIdx.z;
    int tn = t & 15, tm = t >> 4;           // tn -> d (coalesced out), tm -> m(l)
    float acc[4][4] = {};
    const float* xb = x + (size_t)b * CIN * HWSZ;
    for (int k0 = 0; k0 < CIN; k0 += 16) {
        #pragma unroll
        for (int i = 0; i < 4; i++){
            int idx = t + (i<<8);
            int kk = idx >> 6, m = idx & 63;
            As[kk][m] = xb[(size_t)(k0+kk)*HWSZ + l0 + m];
        }
        #pragma unroll
        for (int i = 0; i < 4; i++){
            int idx = t + (i<<8);
            int kk = idx & 15, n = idx >> 4;
            Bs[kk][n] = W[(d0+n)*CIN + k0 + kk];
        }
        __syncthreads();
        #pragma unroll
        for (int kk = 0; kk < 16; kk++){
            float4 a = *(const float4*)&As[kk][tm*4];
            float4 bv = *(const float4*)&Bs[kk][tn*4];
            acc[0][0]+=a.x*bv.x; acc[0][1]+=a.x*bv.y; acc[0][2]+=a.x*bv.z; acc[0][3]+=a.x*bv.w;
            acc[1][0]+=a.y*bv.x; acc[1][1]+=a.y*bv.y; acc[1][2]+=a.y*bv.z; acc[1][3]+=a.y*bv.w;
            acc[2][0]+=a.z*bv.x; acc[2][1]+=a.z*bv.y; acc[2][2]+=a.z*bv.z; acc[2][3]+=a.z*bv.w;
            acc[3][0]+=a.w*bv.x; acc[3][1]+=a.w*bv.y; acc[3][2]+=a.w*bv.z; acc[3][3]+=a.w*bv.w;
        }
        __syncthreads();
    }
    float4 bb = *(const float4*)&bias[d0 + tn*4];
    #pragma unroll
    for (int i = 0; i < 4; i++){
        float4 v = make_float4(acc[i][0]+bb.x, acc[i][1]+bb.y, acc[i][2]+bb.z, acc[i][3]+bb.w);
        *(float4*)&g_xalign[((size_t)(b*HWSZ + l0 + tm*4 + i))*DDIM + d0 + tn*4] = v;
    }
}

// ---------------- K3: sem conv + double layernorm ----------------
// dyn smem: As[32*128] | Bs[128*129] | S[32*132] | W1[128] | B1[128] | SB[128]
#define SM3_FLOATS (4096 + 16512 + 4224 + 128 + 128 + 128)
__global__ __launch_bounds__(256) void k_sem_ln(const float* __restrict__ sw,
                                                const float* __restrict__ sb,
                                                const float* __restrict__ n1w,
                                                const float* __restrict__ n1b){
    extern __shared__ float sm[];
    float* As = sm;
    float* Bs = sm + 4096;
    float* S  = sm + 4096 + 16512;
    float* W1 = S + 4224;
    float* B1 = W1 + 128;
    float* SB = B1 + 128;
    int t = threadIdx.x;
    int m0 = blockIdx.x * 32;
    int cg = t & 15, rg = t >> 4;

    #pragma unroll
    for (int i = 0; i < 16; i++){ int idx = t + (i<<8); As[idx] = g_xalign[(size_t)m0*DDIM + idx]; }
    #pragma unroll
    for (int i = 0; i < 64; i++){ int idx = t + (i<<8); Bs[(idx>>7)*129 + (idx&127)] = sw[idx]; }
    if (t < 128){ W1[t] = n1w[t]; B1[t] = n1b[t]; SB[t] = sb[t]; }
    __syncthreads();

    float acc[2][8] = {};
    #pragma unroll 4
    for (int k = 0; k < 128; k++){
        float a0 = As[(rg*2)*128 + k];
        float a1 = As[(rg*2+1)*128 + k];
        #pragma unroll
        for (int j = 0; j < 8; j++){
            float bv = Bs[(cg + (j<<4))*129 + k];
            acc[0][j] += a0*bv; acc[1][j] += a1*bv;
        }
    }
    #pragma unroll
    for (int i = 0; i < 2; i++)
        #pragma unroll
        for (int j = 0; j < 8; j++)
            S[(rg*2+i)*132 + cg + (j<<4)] = acc[i][j] + SB[cg + (j<<4)];
    __syncthreads();

    int w = t >> 5, lane = t & 31;
    #pragma unroll
    for (int rr = 0; rr < 4; rr++){
        int r = w + (rr<<3);
        float v[4];
        #pragma unroll
        for (int p = 0; p < 4; p++) v[p] = S[r*132 + lane + (p<<5)];
        float mean = wSum(v[0]+v[1]+v[2]+v[3]) * (1.f/DDIM);
        float q = 0.f;
        #pragma unroll
        for (int p = 0; p < 4; p++){ float d = v[p]-mean; q += d*d; }
        float rstd = rsqrtf(wSum(q)*(1.f/DDIM) + LN_EPS);
        float ln1[4]; float ss = 0.f, s2 = 0.f;
        #pragma unroll
        for (int p = 0; p < 4; p++){
            int dd = lane + (p<<5);
            ln1[p] = (v[p]-mean)*rstd*W1[dd] + B1[dd];
            ss += ln1[p]*ln1[p]; s2 += ln1[p];
        }
        float cdlinv = rsqrtf(wSum(ss));
        float m2 = wSum(s2) * (1.f/DDIM);
        float q2 = 0.f;
        #pragma unroll
        for (int p = 0; p < 4; p++){ float d = ln1[p]-m2; q2 += d*d; }
        float rstd2 = rsqrtf(wSum(q2)*(1.f/DDIM) + LN_EPS);
        #pragma unroll
        for (int p = 0; p < 4; p++){
            int dd = lane + (p<<5);
            g_ln2[(size_t)(m0+r)*DDIM + dd] = (ln1[p]-m2)*rstd2*W1[dd] + B1[dd];
        }
        if (lane == 0) g_cdlinv[m0+r] = cdlinv;
    }
}

// ---------------- K4: sim GEMM + softmax + degrad GEMM (fused) ----------------
// dyn smem: As[32*128] | cdl[32] | Bs[128*129] | P[32*520] | rn[128]
#define SM4_FLOATS (4096 + 32 + 16512 + 16640 + 128)
__global__ __launch_bounds__(256) void k_sim(){
    extern __shared__ float sm[];
    float* As  = sm;
    float* cdl = sm + 4096;
    float* Bs  = cdl + 32;
    float* P   = Bs + 16512;
    float* rn  = P + 16640;
    int t = threadIdx.x;
    int m0 = blockIdx.x * 32;
    int cg = t & 15, rg = t >> 4;

    #pragma unroll
    for (int i = 0; i < 16; i++){ int idx = t + (i<<8); As[idx] = g_ln2[(size_t)m0*DDIM + idx]; }
    if (t < 32) cdl[t] = g_cdlinv[m0 + t];
    __syncthreads();

    // ---- sim tiles -> P ----
    for (int nt = 0; nt < 4; nt++){
        if (nt > 0) __syncthreads();
        #pragma unroll
        for (int i = 0; i < 64; i++){
            int idx = t + (i<<8);
            Bs[(idx>>7)*129 + (idx&127)] = g_dr_ln[(size_t)(nt*128)*DDIM + idx];
        }
        if (t < 128) rn[t] = g_dr_rnorm[nt*128 + t];
        __syncthreads();
        float acc[2][8] = {};
        #pragma unroll 4
        for (int k = 0; k < 128; k++){
            float a0 = As[(rg*2)*128 + k];
            float a1 = As[(rg*2+1)*128 + k];
            #pragma unroll
            for (int j = 0; j < 8; j++){
                float bv = Bs[(cg + (j<<4))*129 + k];
                acc[0][j] += a0*bv; acc[1][j] += a1*bv;
            }
        }
        #pragma unroll
        for (int i = 0; i < 2; i++){
            int r = rg*2 + i; float ci = cdl[r];
            #pragma unroll
            for (int j = 0; j < 8; j++){
                int n = cg + (j<<4);
                P[r*520 + nt*128 + n] = acc[i][j] * ci * rn[n];
            }
        }
    }
    __syncthreads();

    // ---- softmax per row (warp per row, 4 rows/warp) ----
    int w = t >> 5, lane = t & 31;
    #pragma unroll
    for (int rr = 0; rr < 4; rr++){
        int r = w + (rr<<3);
        float vv[16]; float mx = -1e30f;
        #pragma unroll
        for (int p = 0; p < 16; p++){ vv[p] = P[r*520 + lane + (p<<5)]; mx = fmaxf(mx, vv[p]); }
        mx = wMax(mx);
        float s = 0.f;
        #pragma unroll
        for (int p = 0; p < 16; p++){ vv[p] = __expf(vv[p]-mx); s += vv[p]; }
        s = wSum(s);
        float inv = 1.f / s;
        size_t row = m0 + r;
        #pragma unroll
        for (int p = 0; p < 16; p++){
            float val = vv[p]*inv;
            P[r*520 + lane + (p<<5)] = val;
            g_sim[row*NTOK + lane + (p<<5)] = val;
        }
        if (lane == 0) g_rowmax[row] = inv;   // max prob = exp(0)/sum
    }
    __syncthreads();

    // ---- degrad: deg[r][d] = sum_n P[r][n] * dr_ln[n][d] ----
    float acc2[2][8] = {};
    for (int nt = 0; nt < 4; nt++){
        __syncthreads();
        #pragma unroll
        for (int i = 0; i < 64; i++){
            int idx = t + (i<<8);
            Bs[(idx>>7)*129 + (idx&127)] = g_dr_ln[(size_t)(nt*128)*DDIM + idx];
        }
        __syncthreads();
        #pragma unroll 4
        for (int nn = 0; nn < 128; nn++){
            float p0 = P[(rg*2)*520 + nt*128 + nn];
            float p1 = P[(rg*2+1)*520 + nt*128 + nn];
            #pragma unroll
            for (int j = 0; j < 8; j++){
                float bv = Bs[nn*129 + cg + (j<<4)];
                acc2[0][j] += p0*bv; acc2[1][j] += p1*bv;
            }
        }
    }
    #pragma unroll
    for (int i = 0; i < 2; i++)
        #pragma unroll
        for (int j = 0; j < 8; j++)
            g_degrad[(size_t)(m0 + rg*2 + i)*DDIM + cg + (j<<4)] = acc2[i][j];
}

// ---------------- K5: per-batch min/max mask + top-81 selection ----------------
__global__ __launch_bounds__(256) void k_topk_mask(float* __restrict__ outp){
    __shared__ float sv[HWSZ];
    __shared__ unsigned long long red[256];
    __shared__ float redf[256];
    __shared__ float s_mn, s_mx;
    int b = blockIdx.x, t = threadIdx.x;
    float mn = 1e30f, mx = -1e30f;
    #pragma unroll
    for (int i = 0; i < 16; i++){
        float v = g_rowmax[b*HWSZ + t + (i<<8)];
        sv[t + (i<<8)] = v;
        mn = fminf(mn, v); mx = fmaxf(mx, v);
    }
    redf[t] = mn; __syncthreads();
    for (int s = 128; s; s >>= 1){ if (t < s) redf[t] = fminf(redf[t], redf[t+s]); __syncthreads(); }
    if (t == 0) s_mn = redf[0];
    __syncthreads();
    redf[t] = mx; __syncthreads();
    for (int s = 128; s; s >>= 1){ if (t < s) redf[t] = fmaxf(redf[t], redf[t+s]); __syncthreads(); }
    if (t == 0) s_mx = redf[0];
    __syncthreads();
    float mn3 = s_mn*s_mn*s_mn, mx3 = s_mx*s_mx*s_mx;
    float inv = 1.f / (mx3 - mn3);
    #pragma unroll
    for (int i = 0; i < 16; i++){
        int l = t + (i<<8);
        float v = sv[l];
        outp[OUT_MASK + b*HWSZ + l] = 1.f - (v*v*v - mn3) * inv;
    }
    // iterative top-81, tie -> lowest index (probs are strictly > 0; removed=0)
    for (int it = 0; it < KSEL; it++){
        unsigned long long best = 0ull;
        #pragma unroll
        for (int i = 0; i < 16; i++){
            int l = t + (i<<8);
            unsigned long long key =
                ((unsigned long long)__float_as_uint(sv[l]) << 32) | (unsigned)(0xFFFFFFFFu - (unsigned)l);
            if (key > best) best = key;
        }
        red[t] = best; __syncthreads();
        for (int s = 128; s; s >>= 1){
            if (t < s){ if (red[t+s] > red[t]) red[t] = red[t+s]; }
            __syncthreads();
        }
        if (t == 0){
            int idx = (int)(0xFFFFFFFFu - (unsigned)(red[0] & 0xFFFFFFFFull));
            g_topidx[b*KSEL + it] = idx;
            sv[idx] = 0.f;
        }
        __syncthreads();
    }
}

// ---------------- K7: gather results rows ----------------
__global__ __launch_bounds__(128) void k_gather(float* __restrict__ outp){
    int g = blockIdx.x;                    // b*648 + i*81 + k
    int b = g / (BTOT*KSEL);
    int rem = g - b*(BTOT*KSEL);
    int i = rem / KSEL, k = rem - i*KSEL;
    int src = g_topidx[i*KSEL + k];
    const float4* s = (const float4*)&g_sim[((size_t)(b*HWSZ + src))*NTOK];
    float4* o = (float4*)&outp[OUT_RES + (size_t)g*NTOK];
    o[threadIdx.x] = s[threadIdx.x];
}

// ---------------- K6: conv_out GEMM  degrad[m,d] * Wout[o,d] -> out[b,o,l] ----------------
__global__ __launch_bounds__(256) void k_conv_out(const float* __restrict__ W,
                                                  const float* __restrict__ bias,
                                                  float* __restrict__ outp){
    __shared__ float As[16][68];   // [k][m(l)]
    __shared__ float Bs[16][68];   // [k][o]
    int t = threadIdx.x;
    int l0 = blockIdx.x * 64, o0 = blockIdx.y * 64, b = blockIdx.z;
    int tn = t & 15, tm = t >> 4;           // tn -> l (coalesced out), tm -> o
    float acc[4][4] = {};
    for (int k0 = 0; k0 < DDIM; k0 += 16){
        #pragma unroll
        for (int i = 0; i < 4; i++){
            int idx = t + (i<<8);
            int kk = idx & 15, m = idx >> 4;
            As[kk][m] = g_degrad[((size_t)(b*HWSZ + l0 + m))*DDIM + k0 + kk];
        }
        #pragma unroll
        for (int i = 0; i < 4; i++){
            int idx = t + (i<<8);
            int kk = idx & 15, n = idx >> 4;
            Bs[kk][n] = W[(o0+n)*DDIM + k0 + kk];
        }
        __syncthreads();
        #pragma unroll
        for (int kk = 0; kk < 16; kk++){
            float4 a = *(const float4*)&As[kk][tn*4];   // over l
            float4 bv = *(const float4*)&Bs[kk][tm*4];  // over o
            acc[0][0]+=bv.x*a.x; acc[0][1]+=bv.x*a.y; acc[0][2]+=bv.x*a.z; acc[0][3]+=bv.x*a.w;
            acc[1][0]+=bv.y*a.x; acc[1][1]+=bv.y*a.y; acc[1][2]+=bv.y*a.z; acc[1][3]+=bv.y*a.w;
            acc[2][0]+=bv.z*a.x; acc[2][1]+=bv.z*a.y; acc[2][2]+=bv.z*a.z; acc[2][3]+=bv.z*a.w;
            acc[3][0]+=bv.w*a.x; acc[3][1]+=bv.w*a.y; acc[3][2]+=bv.w*a.z; acc[3][3]+=bv.w*a.w;
        }
        __syncthreads();
    }
    #pragma unroll
    for (int i = 0; i < 4; i++){
        int o = o0 + tm*4 + i;
        float bb = bias[o];
        float4 v = make_float4(acc[i][0]+bb, acc[i][1]+bb, acc[i][2]+bb, acc[i][3]+bb);
        *(float4*)&outp[OUT_IMG + ((size_t)(b*CIN + o))*HWSZ + l0 + tn*4] = v;
    }
}

// ---------------- launch ----------------
extern "C" void kernel_launch(void* const* d_in, const int* in_sizes, int n_in,
                              void* d_out, int out_size){
    const float* x   = (const float*)d_in[0];
    const float* DRp = (const float*)d_in[1];
    const float* ciw = (const float*)d_in[2];
    const float* cib = (const float*)d_in[3];
    const float* sw  = (const float*)d_in[4];
    const float* sb  = (const float*)d_in[5];
    const float* n1w = (const float*)d_in[6];
    const float* n1b = (const float*)d_in[7];
    const float* n2w = (const float*)d_in[8];
    const float* n2b = (const float*)d_in[9];
    const float* cow = (const float*)d_in[10];
    const float* cob = (const float*)d_in[11];
    float* out = (float*)d_out;

    cudaFuncSetAttribute(k_sem_ln, cudaFuncAttributeMaxDynamicSharedMemorySize, SM3_FLOATS*4);
    cudaFuncSetAttribute(k_sim,    cudaFuncAttributeMaxDynamicSharedMemorySize, SM4_FLOATS*4);

    k_ln_dr   <<<NTOK, 128>>>(DRp, n2w, n2b);
    k_conv_in <<<dim3(HWSZ/64, DDIM/64, BTOT), 256>>>(x, ciw, cib);
    k_sem_ln  <<<MROW/32, 256, SM3_FLOATS*4>>>(sw, sb, n1w, n1b);
    k_sim     <<<MROW/32, 256, SM4_FLOATS*4>>>();
    k_topk_mask<<<BTOT, 256>>>(out);
    k_gather  <<<BTOT*BTOT*KSEL, 128>>>(out);
    k_conv_out<<<dim3(HWSZ/64, CIN/64, BTOT), 256>>>(cow, cob, out);
}

// round 3
// speedup vs baseline: 1.7478x; 1.7478x over previous
#include <cuda_runtime.h>
#include <cuda_bf16.h>
#include <cstdint>

#define BTOT 8
#define CIN  384
#define HWSZ 4096
#define DDIM 128
#define NTOK 512
#define MROW (BTOT*HWSZ)   // 32768
#define KSEL 81
#define LN_EPS 1e-5f

// Output layout in d_out (float32): mask [8,1,64,64] | out_img [8,384,64,64] | results [8,8,81,512]
#define OUT_MASK 0
#define OUT_IMG  32768
#define OUT_RES  (32768 + BTOT*CIN*HWSZ)

// ---------------- scratch ----------------
__device__ float g_xalign[(size_t)MROW*DDIM];
__device__ __nv_bfloat16 g_ln2hi[(size_t)MROW*DDIM];  // ln(ln(sem(x))) * cdlinv, hi
__device__ __nv_bfloat16 g_ln2lo[(size_t)MROW*DDIM];  // lo
__device__ __nv_bfloat16 g_drS_hi[NTOK*DDIM];         // ln(DR)[n][d]*rn[n]
__device__ __nv_bfloat16 g_drS_lo[NTOK*DDIM];
__device__ __nv_bfloat16 g_drT_hi[DDIM*NTOK];         // ln(DR) transposed [d][n]
__device__ __nv_bfloat16 g_drT_lo[DDIM*NTOK];
__device__ float g_simE[(size_t)MROW*NTOK];           // unnormalized exp(sim)
__device__ float g_rowinv[MROW];                      // 1/sum(exp)
__device__ float g_rowmax[MROW];                      // max softmax prob
__device__ float g_degrad[(size_t)MROW*DDIM];
__device__ int   g_topidx[BTOT*KSEL];

// ---------------- helpers ----------------
__device__ __forceinline__ uint32_t smem_u32(const void* p){
    uint32_t a; asm("{ .reg .u64 t; cvta.to.shared.u64 t, %1; cvt.u32.u64 %0, t; }" : "=r"(a) : "l"(p));
    return a;
}
__device__ __forceinline__ void ldmx4(uint32_t* r, uint32_t addr){
    asm volatile("ldmatrix.sync.aligned.m8n8.x4.shared.b16 {%0,%1,%2,%3}, [%4];"
        : "=r"(r[0]),"=r"(r[1]),"=r"(r[2]),"=r"(r[3]) : "r"(addr));
}
__device__ __forceinline__ void ldmx2(uint32_t* r, uint32_t addr){
    asm volatile("ldmatrix.sync.aligned.m8n8.x2.shared.b16 {%0,%1}, [%2];"
        : "=r"(r[0]),"=r"(r[1]) : "r"(addr));
}
__device__ __forceinline__ void mma16816(float* c, const uint32_t* a, const uint32_t* b){
    asm volatile("mma.sync.aligned.m16n8k16.row.col.f32.bf16.bf16.f32 "
        "{%0,%1,%2,%3},{%4,%5,%6,%7},{%8,%9},{%0,%1,%2,%3};"
        : "+f"(c[0]),"+f"(c[1]),"+f"(c[2]),"+f"(c[3])
        : "r"(a[0]),"r"(a[1]),"r"(a[2]),"r"(a[3]),"r"(b[0]),"r"(b[1]));
}
__device__ __forceinline__ uint32_t pack_bf2(float a, float b){
    __nv_bfloat162 t = __floats2bfloat162_rn(a,b);
    return *(uint32_t*)&t;
}
// copy a 128x128 bf16 tile (gmem row-major, stride elems) to smem rows padded to 136 bf16 (272B)
__device__ __forceinline__ void stage136(char* dst, const __nv_bfloat16* __restrict__ src, int stride){
    int t = threadIdx.x;
    #pragma unroll
    for (int i = 0; i < 8; i++){
        int idx = t + (i<<8);
        int row = idx >> 4, c8 = (idx & 15) << 3;
        *(uint4*)(dst + row*272 + c8*2) = *(const uint4*)(src + (size_t)row*stride + c8);
    }
}
// A-fragment ldmatrix address (16x16 tile at tileBase, k-offset k0)
__device__ __forceinline__ uint32_t aAddr(uint32_t tileBase, int k0, int lane){
    return tileBase + (uint32_t)(lane & 15)*272u + (uint32_t)(k0 + ((lane>>4)<<3))*2u;
}
// B-fragment ldmatrix address ([n][k] row-major tile at base, n-offset n0, k-offset k0)
__device__ __forceinline__ uint32_t bAddr(uint32_t base, int n0, int k0, int lane){
    int l = lane & 15;
    return base + (uint32_t)(n0 + (l & 7))*272u + (uint32_t)(k0 + ((l>>3)&1)*8)*2u;
}

__device__ __forceinline__ float wSum(float v){
    #pragma unroll
    for (int o=16;o;o>>=1) v += __shfl_xor_sync(0xFFFFFFFFu, v, o);
    return v;
}
__device__ __forceinline__ float qSum(float v){
    v += __shfl_xor_sync(0xFFFFFFFFu, v, 1);
    v += __shfl_xor_sync(0xFFFFFFFFu, v, 2);
    return v;
}
__device__ __forceinline__ float qMax(float v){
    v = fmaxf(v, __shfl_xor_sync(0xFFFFFFFFu, v, 1));
    v = fmaxf(v, __shfl_xor_sync(0xFFFFFFFFu, v, 2));
    return v;
}
__device__ __forceinline__ float blockSum128(float v, float* red){
    v = wSum(v);
    int w = threadIdx.x >> 5;
    if ((threadIdx.x & 31) == 0) red[w] = v;
    __syncthreads();
    float s = red[0] + red[1] + red[2] + red[3];
    __syncthreads();
    return s;
}

// ---------------- K1: layernorm of DR rows, bf16-split outputs ----------------
__global__ void k_ln_dr(const float* __restrict__ DRp,
                        const float* __restrict__ w2, const float* __restrict__ b2){
    __shared__ float red[4];
    int n = blockIdx.x, t = threadIdx.x;   // 128 threads
    float v = DRp[n*DDIM + t];
    float mean = blockSum128(v, red) * (1.f/DDIM);
    float d = v - mean;
    float var = blockSum128(d*d, red) * (1.f/DDIM);
    float rstd = rsqrtf(var + LN_EPS);
    float ln = d * rstd * w2[t] + b2[t];
    float ss = blockSum128(ln*ln, red);
    float rn = rsqrtf(ss);
    float s = ln * rn;
    __nv_bfloat16 sh = __float2bfloat16(s);
    g_drS_hi[n*DDIM + t] = sh;
    g_drS_lo[n*DDIM + t] = __float2bfloat16(s - __bfloat162float(sh));
    __nv_bfloat16 th = __float2bfloat16(ln);
    g_drT_hi[t*NTOK + n] = th;
    g_drT_lo[t*NTOK + n] = __float2bfloat16(ln - __bfloat162float(th));
}

// ---------------- K2: conv_in GEMM ----------------
__global__ __launch_bounds__(256) void k_conv_in(const float* __restrict__ x,
                                                 const float* __restrict__ W,
                                                 const float* __restrict__ bias){
    __shared__ float As[16][64];
    __shared__ float Bs[16][68];
    int t = threadIdx.x;
    int l0 = blockIdx.x * 64, d0 = blockIdx.y * 64, b = blockIdx.z;
    int tn = t & 15, tm = t >> 4;
    float acc[4][4] = {};
    const float* xb = x + (size_t)b * CIN * HWSZ;
    for (int k0 = 0; k0 < CIN; k0 += 16) {
        #pragma unroll
        for (int i = 0; i < 4; i++){
            int idx = t + (i<<8);
            int kk = idx >> 6, m = idx & 63;
            As[kk][m] = xb[(size_t)(k0+kk)*HWSZ + l0 + m];
        }
        #pragma unroll
        for (int i = 0; i < 4; i++){
            int idx = t + (i<<8);
            int kk = idx & 15, n = idx >> 4;
            Bs[kk][n] = W[(d0+n)*CIN + k0 + kk];
        }
        __syncthreads();
        #pragma unroll
        for (int kk = 0; kk < 16; kk++){
            float4 a = *(const float4*)&As[kk][tm*4];
            float4 bv = *(const float4*)&Bs[kk][tn*4];
            acc[0][0]+=a.x*bv.x; acc[0][1]+=a.x*bv.y; acc[0][2]+=a.x*bv.z; acc[0][3]+=a.x*bv.w;
            acc[1][0]+=a.y*bv.x; acc[1][1]+=a.y*bv.y; acc[1][2]+=a.y*bv.z; acc[1][3]+=a.y*bv.w;
            acc[2][0]+=a.z*bv.x; acc[2][1]+=a.z*bv.y; acc[2][2]+=a.z*bv.z; acc[2][3]+=a.z*bv.w;
            acc[3][0]+=a.w*bv.x; acc[3][1]+=a.w*bv.y; acc[3][2]+=a.w*bv.z; acc[3][3]+=a.w*bv.w;
        }
        __syncthreads();
    }
    float4 bb = *(const float4*)&bias[d0 + tn*4];
    #pragma unroll
    for (int i = 0; i < 4; i++){
        float4 v = make_float4(acc[i][0]+bb.x, acc[i][1]+bb.y, acc[i][2]+bb.z, acc[i][3]+bb.w);
        *(float4*)&g_xalign[((size_t)(b*HWSZ + l0 + tm*4 + i))*DDIM + d0 + tn*4] = v;
    }
}

// ---------------- K3: sem conv + double layernorm -> bf16 split (prescaled by cdlinv) ----------------
#define SM3_FLOATS (4096 + 16512 + 4224 + 128 + 128 + 128)
__global__ __launch_bounds__(256) void k_sem_ln(const float* __restrict__ sw,
                                                const float* __restrict__ sb,
                                                const float* __restrict__ n1w,
                                                const float* __restrict__ n1b){
    extern __shared__ float sm[];
    float* As = sm;
    float* Bs = sm + 4096;
    float* S  = sm + 4096 + 16512;
    float* W1 = S + 4224;
    float* B1 = W1 + 128;
    float* SB = B1 + 128;
    int t = threadIdx.x;
    int m0 = blockIdx.x * 32;
    int cg = t & 15, rg = t >> 4;

    #pragma unroll
    for (int i = 0; i < 16; i++){ int idx = t + (i<<8); As[idx] = g_xalign[(size_t)m0*DDIM + idx]; }
    #pragma unroll
    for (int i = 0; i < 64; i++){ int idx = t + (i<<8); Bs[(idx>>7)*129 + (idx&127)] = sw[idx]; }
    if (t < 128){ W1[t] = n1w[t]; B1[t] = n1b[t]; SB[t] = sb[t]; }
    __syncthreads();

    float acc[2][8] = {};
    #pragma unroll 4
    for (int k = 0; k < 128; k++){
        float a0 = As[(rg*2)*128 + k];
        float a1 = As[(rg*2+1)*128 + k];
        #pragma unroll
        for (int j = 0; j < 8; j++){
            float bv = Bs[(cg + (j<<4))*129 + k];
            acc[0][j] += a0*bv; acc[1][j] += a1*bv;
        }
    }
    #pragma unroll
    for (int i = 0; i < 2; i++)
        #pragma unroll
        for (int j = 0; j < 8; j++)
            S[(rg*2+i)*132 + cg + (j<<4)] = acc[i][j] + SB[cg + (j<<4)];
    __syncthreads();

    int w = t >> 5, lane = t & 31;
    #pragma unroll
    for (int rr = 0; rr < 4; rr++){
        int r = w + (rr<<3);
        float v[4];
        #pragma unroll
        for (int p = 0; p < 4; p++) v[p] = S[r*132 + lane + (p<<5)];
        float mean = wSum(v[0]+v[1]+v[2]+v[3]) * (1.f/DDIM);
        float q = 0.f;
        #pragma unroll
        for (int p = 0; p < 4; p++){ float d = v[p]-mean; q += d*d; }
        float rstd = rsqrtf(wSum(q)*(1.f/DDIM) + LN_EPS);
        float ln1[4]; float ss = 0.f, s2 = 0.f;
        #pragma unroll
        for (int p = 0; p < 4; p++){
            int dd = lane + (p<<5);
            ln1[p] = (v[p]-mean)*rstd*W1[dd] + B1[dd];
            ss += ln1[p]*ln1[p]; s2 += ln1[p];
        }
        float cdlinv = rsqrtf(wSum(ss));
        float m2 = wSum(s2) * (1.f/DDIM);
        float q2 = 0.f;
        #pragma unroll
        for (int p = 0; p < 4; p++){ float d = ln1[p]-m2; q2 += d*d; }
        float rstd2 = rsqrtf(wSum(q2)*(1.f/DDIM) + LN_EPS);
        #pragma unroll
        for (int p = 0; p < 4; p++){
            int dd = lane + (p<<5);
            float y = ((ln1[p]-m2)*rstd2*W1[dd] + B1[dd]) * cdlinv;
            __nv_bfloat16 h = __float2bfloat16(y);
            size_t o = (size_t)(m0+r)*DDIM + dd;
            g_ln2hi[o] = h;
            g_ln2lo[o] = __float2bfloat16(y - __bfloat162float(h));
        }
    }
}

// ---------------- K4: fused sim GEMM + softmax + degrad GEMM (mma.sync bf16 split) ----------------
// smem: Ahi|Alo|B1hi|B1lo|B2hi|B2lo, each 128x136 bf16 = 34816 B -> 208896 B
#define SMEM_SIM 208896
__global__ __launch_bounds__(256,1) void k_sim(){
    extern __shared__ char smem[];
    uint32_t sb = smem_u32(smem);
    int t = threadIdx.x, lane = t & 31, w = t >> 5;
    int m0 = blockIdx.x * 128;

    uint32_t o_Ahi = sb, o_Alo = sb + 34816;
    uint32_t o_B1h = sb + 69632, o_B1l = sb + 104448;
    uint32_t o_B2h = sb + 139264, o_B2l = sb + 174080;

    stage136(smem,          g_ln2hi + (size_t)m0*DDIM, DDIM);
    stage136(smem + 34816,  g_ln2lo + (size_t)m0*DDIM, DDIM);

    uint32_t aTh = o_Ahi + (uint32_t)(w*16)*272u;
    uint32_t aTl = o_Alo + (uint32_t)(w*16)*272u;
    int rlo = m0 + w*16 + (lane >> 2), rhi = rlo + 8;

    float acc2[16][4] = {};
    float sum_lo = 0.f, sum_hi = 0.f, emax_lo = 0.f, emax_hi = 0.f;

    for (int c = 0; c < 4; c++){
        __syncthreads();
        stage136(smem + 69632,  g_drS_hi + (size_t)c*128*DDIM, DDIM);
        stage136(smem + 104448, g_drS_lo + (size_t)c*128*DDIM, DDIM);
        stage136(smem + 139264, g_drT_hi + c*128, NTOK);
        stage136(smem + 174080, g_drT_lo + c*128, NTOK);
        __syncthreads();

        // ---- phase 1: logits for 128 rows x 128 cols ----
        float acc[16][4] = {};
        #pragma unroll
        for (int ks = 0; ks < 8; ks++){
            uint32_t ah[4], al[4];
            ldmx4(ah, aAddr(aTh, ks*16, lane));
            ldmx4(al, aAddr(aTl, ks*16, lane));
            #pragma unroll
            for (int j = 0; j < 16; j++){
                uint32_t bh[2], bl[2];
                ldmx2(bh, bAddr(o_B1h, j*8, ks*16, lane));
                ldmx2(bl, bAddr(o_B1l, j*8, ks*16, lane));
                mma16816(acc[j], ah, bh);
                mma16816(acc[j], ah, bl);
                mma16816(acc[j], al, bh);
            }
        }

        // ---- exp + sums + gmem store + pack to bf16 hi/lo fragments ----
        uint32_t ehi[16][2], elo[16][2];
        #pragma unroll
        for (int j = 0; j < 16; j++){
            float e0 = __expf(acc[j][0]), e1 = __expf(acc[j][1]);
            float e2 = __expf(acc[j][2]), e3 = __expf(acc[j][3]);
            sum_lo += e0 + e1; sum_hi += e2 + e3;
            emax_lo = fmaxf(emax_lo, fmaxf(e0, e1));
            emax_hi = fmaxf(emax_hi, fmaxf(e2, e3));
            int col = c*128 + j*8 + 2*(lane & 3);
            *(float2*)&g_simE[(size_t)rlo*NTOK + col] = make_float2(e0, e1);
            *(float2*)&g_simE[(size_t)rhi*NTOK + col] = make_float2(e2, e3);
            float h0 = __bfloat162float(__float2bfloat16(e0));
            float h1 = __bfloat162float(__float2bfloat16(e1));
            float h2 = __bfloat162float(__float2bfloat16(e2));
            float h3 = __bfloat162float(__float2bfloat16(e3));
            ehi[j][0] = pack_bf2(e0, e1);      ehi[j][1] = pack_bf2(e2, e3);
            elo[j][0] = pack_bf2(e0-h0, e1-h1); elo[j][1] = pack_bf2(e2-h2, e3-h3);
        }

        // ---- phase 2: degrad partial, K = this chunk's 128 n ----
        #pragma unroll
        for (int k = 0; k < 8; k++){
            uint32_t ah[4] = { ehi[2*k][0], ehi[2*k][1], ehi[2*k+1][0], ehi[2*k+1][1] };
            uint32_t al[4] = { elo[2*k][0], elo[2*k][1], elo[2*k+1][0], elo[2*k+1][1] };
            #pragma unroll
            for (int j2 = 0; j2 < 16; j2++){
                uint32_t bh[2], bl[2];
                ldmx2(bh, bAddr(o_B2h, j2*8, k*16, lane));
                ldmx2(bl, bAddr(o_B2l, j2*8, k*16, lane));
                mma16816(acc2[j2], ah, bh);
                mma16816(acc2[j2], ah, bl);
                mma16816(acc2[j2], al, bh);
            }
        }
    }

    // ---- row reductions + epilogue ----
    sum_lo = qSum(sum_lo); sum_hi = qSum(sum_hi);
    emax_lo = qMax(emax_lo); emax_hi = qMax(emax_hi);
    float inv_lo = 1.f / sum_lo, inv_hi = 1.f / sum_hi;
    if ((lane & 3) == 0){
        g_rowinv[rlo] = inv_lo;  g_rowinv[rhi] = inv_hi;
        g_rowmax[rlo] = emax_lo * inv_lo;  g_rowmax[rhi] = emax_hi * inv_hi;
    }
    #pragma unroll
    for (int j2 = 0; j2 < 16; j2++){
        int dcol = j2*8 + 2*(lane & 3);
        *(float2*)&g_degrad[(size_t)rlo*DDIM + dcol] = make_float2(acc2[j2][0]*inv_lo, acc2[j2][1]*inv_lo);
        *(float2*)&g_degrad[(size_t)rhi*DDIM + dcol] = make_float2(acc2[j2][2]*inv_hi, acc2[j2][3]*inv_hi);
    }
}

// ---------------- K5: per-batch min/max mask + top-81 selection ----------------
__global__ __launch_bounds__(256) void k_topk_mask(float* __restrict__ outp){
    __shared__ float sv[HWSZ];
    __shared__ unsigned long long red[256];
    __shared__ float redf[256];
    __shared__ float s_mn, s_mx;
    int b = blockIdx.x, t = threadIdx.x;
    float mn = 1e30f, mx = -1e30f;
    #pragma unroll
    for (int i = 0; i < 16; i++){
        float v = g_rowmax[b*HWSZ + t + (i<<8)];
        sv[t + (i<<8)] = v;
        mn = fminf(mn, v); mx = fmaxf(mx, v);
    }
    redf[t] = mn; __syncthreads();
    for (int s = 128; s; s >>= 1){ if (t < s) redf[t] = fminf(redf[t], redf[t+s]); __syncthreads(); }
    if (t == 0) s_mn = redf[0];
    __syncthreads();
    redf[t] = mx; __syncthreads();
    for (int s = 128; s; s >>= 1){ if (t < s) redf[t] = fmaxf(redf[t], redf[t+s]); __syncthreads(); }
    if (t == 0) s_mx = redf[0];
    __syncthreads();
    float mn3 = s_mn*s_mn*s_mn, mx3 = s_mx*s_mx*s_mx;
    float inv = 1.f / (mx3 - mn3);
    #pragma unroll
    for (int i = 0; i < 16; i++){
        int l = t + (i<<8);
        float v = sv[l];
        outp[OUT_MASK + b*HWSZ + l] = 1.f - (v*v*v - mn3) * inv;
    }
    for (int it = 0; it < KSEL; it++){
        unsigned long long best = 0ull;
        #pragma unroll
        for (int i = 0; i < 16; i++){
            int l = t + (i<<8);
            unsigned long long key =
                ((unsigned long long)__float_as_uint(sv[l]) << 32) | (unsigned)(0xFFFFFFFFu - (unsigned)l);
            if (key > best) best = key;
        }
        red[t] = best; __syncthreads();
        for (int s = 128; s; s >>= 1){
            if (t < s){ if (red[t+s] > red[t]) red[t] = red[t+s]; }
            __syncthreads();
        }
        if (t == 0){
            int idx = (int)(0xFFFFFFFFu - (unsigned)(red[0] & 0xFFFFFFFFull));
            g_topidx[b*KSEL + it] = idx;
            sv[idx] = 0.f;
        }
        __syncthreads();
    }
}

// ---------------- K7: gather result rows (normalize e by rowinv) ----------------
__global__ __launch_bounds__(128) void k_gather(float* __restrict__ outp){
    int g = blockIdx.x;
    int b = g / (BTOT*KSEL);
    int rem = g - b*(BTOT*KSEL);
    int i = rem / KSEL, k = rem - i*KSEL;
    int src = g_topidx[i*KSEL + k];
    size_t row = (size_t)(b*HWSZ + src);
    float inv = g_rowinv[row];
    const float4* s = (const float4*)&g_simE[row*NTOK];
    float4* o = (float4*)&outp[OUT_RES + (size_t)g*NTOK];
    float4 v = s[threadIdx.x];
    v.x *= inv; v.y *= inv; v.z *= inv; v.w *= inv;
    o[threadIdx.x] = v;
}

// ---------------- K6: conv_out GEMM ----------------
__global__ __launch_bounds__(256) void k_conv_out(const float* __restrict__ W,
                                                  const float* __restrict__ bias,
                                                  float* __restrict__ outp){
    __shared__ float As[16][68];
    __shared__ float Bs[16][68];
    int t = threadIdx.x;
    int l0 = blockIdx.x * 64, o0 = blockIdx.y * 64, b = blockIdx.z;
    int tn = t & 15, tm = t >> 4;
    float acc[4][4] = {};
    for (int k0 = 0; k0 < DDIM; k0 += 16){
        #pragma unroll
        for (int i = 0; i < 4; i++){
            int idx = t + (i<<8);
            int kk = idx & 15, m = idx >> 4;
            As[kk][m] = g_degrad[((size_t)(b*HWSZ + l0 + m))*DDIM + k0 + kk];
        }
        #pragma unroll
        for (int i = 0; i < 4; i++){
            int idx = t + (i<<8);
            int kk = idx & 15, n = idx >> 4;
            Bs[kk][n] = W[(o0+n)*DDIM + k0 + kk];
        }
        __syncthreads();
        #pragma unroll
        for (int kk = 0; kk < 16; kk++){
            float4 a = *(const float4*)&As[kk][tn*4];
            float4 bv = *(const float4*)&Bs[kk][tm*4];
            acc[0][0]+=bv.x*a.x; acc[0][1]+=bv.x*a.y; acc[0][2]+=bv.x*a.z; acc[0][3]+=bv.x*a.w;
            acc[1][0]+=bv.y*a.x; acc[1][1]+=bv.y*a.y; acc[1][2]+=bv.y*a.z; acc[1][3]+=bv.y*a.w;
            acc[2][0]+=bv.z*a.x; acc[2][1]+=bv.z*a.y; acc[2][2]+=bv.z*a.z; acc[2][3]+=bv.z*a.w;
            acc[3][0]+=bv.w*a.x; acc[3][1]+=bv.w*a.y; acc[3][2]+=bv.w*a.z; acc[3][3]+=bv.w*a.w;
        }
        __syncthreads();
    }
    #pragma unroll
    for (int i = 0; i < 4; i++){
        int o = o0 + tm*4 + i;
        float bb = bias[o];
        float4 v = make_float4(acc[i][0]+bb, acc[i][1]+bb, acc[i][2]+bb, acc[i][3]+bb);
        *(float4*)&outp[OUT_IMG + ((size_t)(b*CIN + o))*HWSZ + l0 + tn*4] = v;
    }
}

// ---------------- launch ----------------
extern "C" void kernel_launch(void* const* d_in, const int* in_sizes, int n_in,
                              void* d_out, int out_size){
    const float* x   = (const float*)d_in[0];
    const float* DRp = (const float*)d_in[1];
    const float* ciw = (const float*)d_in[2];
    const float* cib = (const float*)d_in[3];
    const float* sw  = (const float*)d_in[4];
    const float* sb  = (const float*)d_in[5];
    const float* n1w = (const float*)d_in[6];
    const float* n1b = (const float*)d_in[7];
    const float* n2w = (const float*)d_in[8];
    const float* n2b = (const float*)d_in[9];
    const float* cow = (const float*)d_in[10];
    const float* cob = (const float*)d_in[11];
    float* out = (float*)d_out;

    cudaFuncSetAttribute(k_sem_ln, cudaFuncAttributeMaxDynamicSharedMemorySize, SM3_FLOATS*4);
    cudaFuncSetAttribute(k_sim,    cudaFuncAttributeMaxDynamicSharedMemorySize, SMEM_SIM);

    k_ln_dr   <<<NTOK, 128>>>(DRp, n2w, n2b);
    k_conv_in <<<dim3(HWSZ/64, DDIM/64, BTOT), 256>>>(x, ciw, cib);
    k_sem_ln  <<<MROW/32, 256, SM3_FLOATS*4>>>(sw, sb, n1w, n1b);
    k_sim     <<<MROW/128, 256, SMEM_SIM>>>();
    k_topk_mask<<<BTOT, 256>>>(out);
    k_gather  <<<BTOT*BTOT*KSEL, 128>>>(out);
    k_conv_out<<<dim3(HWSZ/64, CIN/64, BTOT), 256>>>(cow, cob, out);
}

// round 4
// speedup vs baseline: 2.6114x; 1.4941x over previous
#include <cuda_runtime.h>
#include <cuda_bf16.h>
#include <cstdint>

#define BTOT 8
#define CIN  384
#define HWSZ 4096
#define DDIM 128
#define NTOK 512
#define MROW (BTOT*HWSZ)   // 32768
#define KSEL 81
#define LN_EPS 1e-5f

#define OUT_MASK 0
#define OUT_IMG  32768
#define OUT_RES  (32768 + BTOT*CIN*HWSZ)

// ---------------- scratch ----------------
__device__ __nv_bfloat16 g_W2hi[DDIM*CIN];            // fused conv_in∘sem weight
__device__ __nv_bfloat16 g_W2lo[DDIM*CIN];
__device__ float g_b2[DDIM];
__device__ __nv_bfloat16 g_wouthi[CIN*DDIM];
__device__ __nv_bfloat16 g_woutlo[CIN*DDIM];
__device__ __nv_bfloat16 g_ln2hi[(size_t)MROW*DDIM];  // ln(ln(sem(x))) * cdlinv
__device__ __nv_bfloat16 g_ln2lo[(size_t)MROW*DDIM];
__device__ __nv_bfloat16 g_drS_hi[NTOK*DDIM];         // ln(DR)[n][d]*rn[n]
__device__ __nv_bfloat16 g_drS_lo[NTOK*DDIM];
__device__ __nv_bfloat16 g_drT_hi[DDIM*NTOK];         // ln(DR) transposed [d][n]
__device__ __nv_bfloat16 g_drT_lo[DDIM*NTOK];
__device__ float g_simE[(size_t)MROW*NTOK];           // unnormalized exp(sim)
__device__ float g_rowinv[MROW];
__device__ float g_rowmax[MROW];
__device__ __nv_bfloat16 g_deghi[(size_t)MROW*DDIM];
__device__ __nv_bfloat16 g_deglo[(size_t)MROW*DDIM];
__device__ int   g_topidx[BTOT*KSEL];

// ---------------- helpers ----------------
__device__ __forceinline__ uint32_t smem_u32(const void* p){
    uint32_t a; asm("{ .reg .u64 t; cvta.to.shared.u64 t, %1; cvt.u32.u64 %0, t; }" : "=r"(a) : "l"(p));
    return a;
}
__device__ __forceinline__ void ldmx4(uint32_t* r, uint32_t addr){
    asm volatile("ldmatrix.sync.aligned.m8n8.x4.shared.b16 {%0,%1,%2,%3}, [%4];"
        : "=r"(r[0]),"=r"(r[1]),"=r"(r[2]),"=r"(r[3]) : "r"(addr));
}
__device__ __forceinline__ void ldmx2(uint32_t* r, uint32_t addr){
    asm volatile("ldmatrix.sync.aligned.m8n8.x2.shared.b16 {%0,%1}, [%2];"
        : "=r"(r[0]),"=r"(r[1]) : "r"(addr));
}
__device__ __forceinline__ void mma16816(float* c, const uint32_t* a, const uint32_t* b){
    asm volatile("mma.sync.aligned.m16n8k16.row.col.f32.bf16.bf16.f32 "
        "{%0,%1,%2,%3},{%4,%5,%6,%7},{%8,%9},{%0,%1,%2,%3};"
        : "+f"(c[0]),"+f"(c[1]),"+f"(c[2]),"+f"(c[3])
        : "r"(a[0]),"r"(a[1]),"r"(a[2]),"r"(a[3]),"r"(b[0]),"r"(b[1]));
}
__device__ __forceinline__ uint32_t pack_bf2(float a, float b){
    __nv_bfloat162 t = __floats2bfloat162_rn(a,b);
    return *(uint32_t*)&t;
}
// copy a 128x128 bf16 tile (gmem row-major, stride elems) to smem rows padded to 272B
__device__ __forceinline__ void stage136(char* dst, const __nv_bfloat16* __restrict__ src, int stride){
    int t = threadIdx.x;
    #pragma unroll
    for (int i = 0; i < 8; i++){
        int idx = t + (i<<8);
        int row = idx >> 4, c8 = (idx & 15) << 3;
        *(uint4*)(dst + row*272 + c8*2) = *(const uint4*)(src + (size_t)row*stride + c8);
    }
}
__device__ __forceinline__ uint32_t aAddr(uint32_t tileBase, int k0, int lane){
    return tileBase + (uint32_t)(lane & 15)*272u + (uint32_t)(k0 + ((lane>>4)<<3))*2u;
}
__device__ __forceinline__ uint32_t bAddr(uint32_t base, int n0, int k0, int lane){
    int l = lane & 15;
    return base + (uint32_t)(n0 + (l & 7))*272u + (uint32_t)(k0 + ((l>>3)&1)*8)*2u;
}
__device__ __forceinline__ float wSum(float v){
    #pragma unroll
    for (int o=16;o;o>>=1) v += __shfl_xor_sync(0xFFFFFFFFu, v, o);
    return v;
}
__device__ __forceinline__ float wMaxF(float v){
    #pragma unroll
    for (int o=16;o;o>>=1) v = fmaxf(v, __shfl_xor_sync(0xFFFFFFFFu, v, o));
    return v;
}
__device__ __forceinline__ float wMinF(float v){
    #pragma unroll
    for (int o=16;o;o>>=1) v = fminf(v, __shfl_xor_sync(0xFFFFFFFFu, v, o));
    return v;
}
__device__ __forceinline__ unsigned long long wMaxU(unsigned long long v){
    #pragma unroll
    for (int o=16;o;o>>=1){
        unsigned long long u = __shfl_xor_sync(0xFFFFFFFFu, v, o);
        if (u > v) v = u;
    }
    return v;
}
__device__ __forceinline__ float qSum(float v){
    v += __shfl_xor_sync(0xFFFFFFFFu, v, 1);
    v += __shfl_xor_sync(0xFFFFFFFFu, v, 2);
    return v;
}
__device__ __forceinline__ float qMax(float v){
    v = fmaxf(v, __shfl_xor_sync(0xFFFFFFFFu, v, 1));
    v = fmaxf(v, __shfl_xor_sync(0xFFFFFFFFu, v, 2));
    return v;
}
__device__ __forceinline__ float blockSum128(float v, float* red){
    v = wSum(v);
    int w = threadIdx.x >> 5;
    if ((threadIdx.x & 31) == 0) red[w] = v;
    __syncthreads();
    float s = red[0] + red[1] + red[2] + red[3];
    __syncthreads();
    return s;
}

// ---------------- K0a: W2 = sem_w @ conv_in_w, b2 = sem_w @ cib + semb ----------------
__global__ __launch_bounds__(384) void k_prep_w2(const float* __restrict__ sw,
                                                 const float* __restrict__ ciw,
                                                 const float* __restrict__ cib,
                                                 const float* __restrict__ semb){
    __shared__ float srow[128];
    int o = blockIdx.x, t = threadIdx.x;
    if (t < 128) srow[t] = sw[o*DDIM + t];
    __syncthreads();
    float acc = 0.f;
    #pragma unroll 4
    for (int d = 0; d < 128; d++) acc += srow[d] * ciw[d*CIN + t];
    __nv_bfloat16 h = __float2bfloat16(acc);
    g_W2hi[o*CIN + t] = h;
    g_W2lo[o*CIN + t] = __float2bfloat16(acc - __bfloat162float(h));
    if (t == 0){
        float bacc = 0.f;
        for (int d = 0; d < 128; d++) bacc += srow[d] * cib[d];
        g_b2[o] = bacc + semb[o];
    }
}
// ---------------- K0b: split Wout to bf16 hi/lo ----------------
__global__ __launch_bounds__(256) void k_prep_wout(const float* __restrict__ cow){
    int id = blockIdx.x*256 + threadIdx.x;
    float v = cow[id];
    __nv_bfloat16 h = __float2bfloat16(v);
    g_wouthi[id] = h;
    g_woutlo[id] = __float2bfloat16(v - __bfloat162float(h));
}

// ---------------- K1: layernorm of DR rows ----------------
__global__ void k_ln_dr(const float* __restrict__ DRp,
                        const float* __restrict__ w2, const float* __restrict__ b2){
    __shared__ float red[4];
    int n = blockIdx.x, t = threadIdx.x;
    float v = DRp[n*DDIM + t];
    float mean = blockSum128(v, red) * (1.f/DDIM);
    float d = v - mean;
    float var = blockSum128(d*d, red) * (1.f/DDIM);
    float rstd = rsqrtf(var + LN_EPS);
    float ln = d * rstd * w2[t] + b2[t];
    float ss = blockSum128(ln*ln, red);
    float rn = rsqrtf(ss);
    float s = ln * rn;
    __nv_bfloat16 sh = __float2bfloat16(s);
    g_drS_hi[n*DDIM + t] = sh;
    g_drS_lo[n*DDIM + t] = __float2bfloat16(s - __bfloat162float(sh));
    __nv_bfloat16 th = __float2bfloat16(ln);
    g_drT_hi[t*NTOK + n] = th;
    g_drT_lo[t*NTOK + n] = __float2bfloat16(ln - __bfloat162float(th));
}

// ---------------- K2: fused (conv_in∘sem) GEMM + double-LN epilogue (HMMA) ----------------
// smem: Axhi|Axlo|Bh|Bl (4x34816) + W1[128]+B1[128]+b2[128]
#define SMEM_SEM (139264 + 1536)
__global__ __launch_bounds__(256,1) void k_sem(const float* __restrict__ x,
                                               const float* __restrict__ n1w,
                                               const float* __restrict__ n1b){
    extern __shared__ char smem[];
    uint32_t sb = smem_u32(smem);
    int t = threadIdx.x, lane = t & 31, w = t >> 5;
    int m0 = blockIdx.x * 128;
    int b = m0 >> 12, l0 = m0 & 4095;

    uint32_t o_Ah = sb, o_Al = sb + 34816, o_Bh = sb + 69632, o_Bl = sb + 104448;
    float* W1v = (float*)(smem + 139264);
    float* B1v = W1v + 128;
    float* b2v = B1v + 128;
    if (t < 128){ W1v[t] = n1w[t]; B1v[t] = n1b[t]; b2v[t] = g_b2[t]; }

    float acc[16][4] = {};
    const float* xb = x + (size_t)b * CIN * HWSZ + l0;

    for (int ch = 0; ch < 3; ch++){
        if (ch) __syncthreads();
        // stage x chunk transposed: smem[l][c] from gmem x[c][l]
        #pragma unroll
        for (int i = 0; i < 16; i++){
            int id = t + (i<<8);
            int cr = id & 127, lq = id >> 7;
            float4 v = *(const float4*)(xb + (size_t)(ch*128 + cr)*HWSZ + 4*lq);
            float f[4] = {v.x, v.y, v.z, v.w};
            #pragma unroll
            for (int j = 0; j < 4; j++){
                __nv_bfloat16 h = __float2bfloat16(f[j]);
                *(__nv_bfloat16*)(smem + (o_Ah - sb) + (4*lq+j)*272 + cr*2) = h;
                *(__nv_bfloat16*)(smem + (o_Al - sb) + (4*lq+j)*272 + cr*2) = __float2bfloat16(f[j] - __bfloat162float(h));
            }
        }
        // stage W2 chunk [d][128c]
        #pragma unroll
        for (int i = 0; i < 8; i++){
            int idx = t + (i<<8);
            int row = idx >> 4, c8 = (idx & 15) << 3;
            *(uint4*)(smem + (o_Bh - sb) + row*272 + c8*2) = *(const uint4*)(g_W2hi + row*CIN + ch*128 + c8);
            *(uint4*)(smem + (o_Bl - sb) + row*272 + c8*2) = *(const uint4*)(g_W2lo + row*CIN + ch*128 + c8);
        }
        __syncthreads();
        uint32_t aTh = o_Ah + (uint32_t)(w*16)*272u;
        uint32_t aTl = o_Al + (uint32_t)(w*16)*272u;
        #pragma unroll
        for (int ks = 0; ks < 8; ks++){
            uint32_t ah[4], al[4];
            ldmx4(ah, aAddr(aTh, ks*16, lane));
            ldmx4(al, aAddr(aTl, ks*16, lane));
            #pragma unroll
            for (int j = 0; j < 16; j++){
                uint32_t bh[2], bl[2];
                ldmx2(bh, bAddr(o_Bh, j*8, ks*16, lane));
                ldmx2(bl, bAddr(o_Bl, j*8, ks*16, lane));
                mma16816(acc[j], ah, bh);
                mma16816(acc[j], ah, bl);
                mma16816(acc[j], al, bh);
            }
        }
    }

    // ---- double-LN epilogue; rows = pixels ----
    int gid = lane >> 2, tig = lane & 3;
    #pragma unroll
    for (int half = 0; half < 2; half++){
        int r = m0 + w*16 + gid + half*8;
        float v[32];
        #pragma unroll
        for (int j = 0; j < 16; j++){
            int col = j*8 + 2*tig;
            v[2*j]   = acc[j][2*half]   + b2v[col];
            v[2*j+1] = acc[j][2*half+1] + b2v[col+1];
        }
        float s = 0.f;
        #pragma unroll
        for (int k = 0; k < 32; k++) s += v[k];
        float mean = qSum(s) * (1.f/DDIM);
        float q = 0.f;
        #pragma unroll
        for (int k = 0; k < 32; k++){ float d = v[k]-mean; q += d*d; }
        float rstd = rsqrtf(qSum(q)*(1.f/DDIM) + LN_EPS);
        float ln1[32]; float ss = 0.f, s2 = 0.f;
        #pragma unroll
        for (int j = 0; j < 16; j++){
            int col = j*8 + 2*tig;
            #pragma unroll
            for (int u = 0; u < 2; u++){
                float y = (v[2*j+u]-mean)*rstd*W1v[col+u] + B1v[col+u];
                ln1[2*j+u] = y; ss += y*y; s2 += y;
            }
        }
        float cdlinv = rsqrtf(qSum(ss));
        float m2 = qSum(s2) * (1.f/DDIM);
        float q2 = 0.f;
        #pragma unroll
        for (int k = 0; k < 32; k++){ float d = ln1[k]-m2; q2 += d*d; }
        float rstd2 = rsqrtf(qSum(q2)*(1.f/DDIM) + LN_EPS);
        #pragma unroll
        for (int j = 0; j < 16; j++){
            int col = j*8 + 2*tig;
            float y0 = ((ln1[2*j]-m2)*rstd2*W1v[col] + B1v[col]) * cdlinv;
            float y1 = ((ln1[2*j+1]-m2)*rstd2*W1v[col+1] + B1v[col+1]) * cdlinv;
            float h0 = __bfloat162float(__float2bfloat16(y0));
            float h1 = __bfloat162float(__float2bfloat16(y1));
            *(uint32_t*)&g_ln2hi[(size_t)r*DDIM + col] = pack_bf2(y0, y1);
            *(uint32_t*)&g_ln2lo[(size_t)r*DDIM + col] = pack_bf2(y0-h0, y1-h1);
        }
    }
}

// ---------------- K4: fused sim GEMM + softmax + degrad GEMM (HMMA) ----------------
#define SMEM_SIM 208896
__global__ __launch_bounds__(256,1) void k_sim(){
    extern __shared__ char smem[];
    uint32_t sb = smem_u32(smem);
    int t = threadIdx.x, lane = t & 31, w = t >> 5;
    int m0 = blockIdx.x * 128;

    uint32_t o_Ahi = sb, o_Alo = sb + 34816;
    uint32_t o_B1h = sb + 69632, o_B1l = sb + 104448;
    uint32_t o_B2h = sb + 139264, o_B2l = sb + 174080;

    stage136(smem,          g_ln2hi + (size_t)m0*DDIM, DDIM);
    stage136(smem + 34816,  g_ln2lo + (size_t)m0*DDIM, DDIM);

    uint32_t aTh = o_Ahi + (uint32_t)(w*16)*272u;
    uint32_t aTl = o_Alo + (uint32_t)(w*16)*272u;
    int rlo = m0 + w*16 + (lane >> 2), rhi = rlo + 8;

    float acc2[16][4] = {};
    float sum_lo = 0.f, sum_hi = 0.f, emax_lo = 0.f, emax_hi = 0.f;

    for (int c = 0; c < 4; c++){
        __syncthreads();
        stage136(smem + 69632,  g_drS_hi + (size_t)c*128*DDIM, DDIM);
        stage136(smem + 104448, g_drS_lo + (size_t)c*128*DDIM, DDIM);
        stage136(smem + 139264, g_drT_hi + c*128, NTOK);
        stage136(smem + 174080, g_drT_lo + c*128, NTOK);
        __syncthreads();

        float acc[16][4] = {};
        #pragma unroll
        for (int ks = 0; ks < 8; ks++){
            uint32_t ah[4], al[4];
            ldmx4(ah, aAddr(aTh, ks*16, lane));
            ldmx4(al, aAddr(aTl, ks*16, lane));
            #pragma unroll
            for (int j = 0; j < 16; j++){
                uint32_t bh[2], bl[2];
                ldmx2(bh, bAddr(o_B1h, j*8, ks*16, lane));
                ldmx2(bl, bAddr(o_B1l, j*8, ks*16, lane));
                mma16816(acc[j], ah, bh);
                mma16816(acc[j], ah, bl);
                mma16816(acc[j], al, bh);
            }
        }

        uint32_t ehi[16][2], elo[16][2];
        #pragma unroll
        for (int j = 0; j < 16; j++){
            float e0 = __expf(acc[j][0]), e1 = __expf(acc[j][1]);
            float e2 = __expf(acc[j][2]), e3 = __expf(acc[j][3]);
            sum_lo += e0 + e1; sum_hi += e2 + e3;
            emax_lo = fmaxf(emax_lo, fmaxf(e0, e1));
            emax_hi = fmaxf(emax_hi, fmaxf(e2, e3));
            int col = c*128 + j*8 + 2*(lane & 3);
            *(float2*)&g_simE[(size_t)rlo*NTOK + col] = make_float2(e0, e1);
            *(float2*)&g_simE[(size_t)rhi*NTOK + col] = make_float2(e2, e3);
            float h0 = __bfloat162float(__float2bfloat16(e0));
            float h1 = __bfloat162float(__float2bfloat16(e1));
            float h2 = __bfloat162float(__float2bfloat16(e2));
            float h3 = __bfloat162float(__float2bfloat16(e3));
            ehi[j][0] = pack_bf2(e0, e1);      ehi[j][1] = pack_bf2(e2, e3);
            elo[j][0] = pack_bf2(e0-h0, e1-h1); elo[j][1] = pack_bf2(e2-h2, e3-h3);
        }

        #pragma unroll
        for (int k = 0; k < 8; k++){
            uint32_t ah[4] = { ehi[2*k][0], ehi[2*k][1], ehi[2*k+1][0], ehi[2*k+1][1] };
            uint32_t al[4] = { elo[2*k][0], elo[2*k][1], elo[2*k+1][0], elo[2*k+1][1] };
            #pragma unroll
            for (int j2 = 0; j2 < 16; j2++){
                uint32_t bh[2], bl[2];
                ldmx2(bh, bAddr(o_B2h, j2*8, k*16, lane));
                ldmx2(bl, bAddr(o_B2l, j2*8, k*16, lane));
                mma16816(acc2[j2], ah, bh);
                mma16816(acc2[j2], ah, bl);
                mma16816(acc2[j2], al, bh);
            }
        }
    }

    sum_lo = qSum(sum_lo); sum_hi = qSum(sum_hi);
    emax_lo = qMax(emax_lo); emax_hi = qMax(emax_hi);
    float inv_lo = 1.f / sum_lo, inv_hi = 1.f / sum_hi;
    if ((lane & 3) == 0){
        g_rowinv[rlo] = inv_lo;  g_rowinv[rhi] = inv_hi;
        g_rowmax[rlo] = emax_lo * inv_lo;  g_rowmax[rhi] = emax_hi * inv_hi;
    }
    #pragma unroll
    for (int j2 = 0; j2 < 16; j2++){
        int dcol = j2*8 + 2*(lane & 3);
        float y0 = acc2[j2][0]*inv_lo, y1 = acc2[j2][1]*inv_lo;
        float y2 = acc2[j2][2]*inv_hi, y3 = acc2[j2][3]*inv_hi;
        float h0 = __bfloat162float(__float2bfloat16(y0));
        float h1 = __bfloat162float(__float2bfloat16(y1));
        float h2 = __bfloat162float(__float2bfloat16(y2));
        float h3 = __bfloat162float(__float2bfloat16(y3));
        *(uint32_t*)&g_deghi[(size_t)rlo*DDIM + dcol] = pack_bf2(y0, y1);
        *(uint32_t*)&g_deglo[(size_t)rlo*DDIM + dcol] = pack_bf2(y0-h0, y1-h1);
        *(uint32_t*)&g_deghi[(size_t)rhi*DDIM + dcol] = pack_bf2(y2, y3);
        *(uint32_t*)&g_deglo[(size_t)rhi*DDIM + dcol] = pack_bf2(y2-h2, y3-h3);
    }
}

// ---------------- K5: mask + top-81 (1024 threads, register values) ----------------
__global__ __launch_bounds__(1024) void k_topk_mask(float* __restrict__ outp){
    __shared__ unsigned long long warr[32];
    __shared__ unsigned long long swin;
    __shared__ float sred[32];
    __shared__ float s_mn, s_mx;
    int b = blockIdx.x, t = threadIdx.x;
    int lane = t & 31, w = t >> 5;
    float v[4];
    float mn = 1e30f, mx = -1e30f;
    #pragma unroll
    for (int i = 0; i < 4; i++){
        v[i] = g_rowmax[b*HWSZ + t + (i<<10)];
        mn = fminf(mn, v[i]); mx = fmaxf(mx, v[i]);
    }
    mn = wMinF(mn);
    if (lane == 0) sred[w] = mn;
    __syncthreads();
    if (w == 0){ float x = wMinF(sred[lane]); if (lane == 0) s_mn = x; }
    __syncthreads();
    mx = wMaxF(mx);
    if (lane == 0) sred[w] = mx;
    __syncthreads();
    if (w == 0){ float x = wMaxF(sred[lane]); if (lane == 0) s_mx = x; }
    __syncthreads();
    float mn3 = s_mn*s_mn*s_mn, mx3 = s_mx*s_mx*s_mx;
    float inv = 1.f / (mx3 - mn3);
    #pragma unroll
    for (int i = 0; i < 4; i++){
        int l = t + (i<<10);
        outp[OUT_MASK + b*HWSZ + l] = 1.f - (v[i]*v[i]*v[i] - mn3) * inv;
    }
    for (int it = 0; it < KSEL; it++){
        unsigned long long best = 0ull;
        #pragma unroll
        for (int i = 0; i < 4; i++){
            int l = t + (i<<10);
            unsigned long long key =
                ((unsigned long long)__float_as_uint(v[i]) << 32) | (unsigned)(0xFFFFFFFFu - (unsigned)l);
            if (key > best) best = key;
        }
        best = wMaxU(best);
        if (lane == 0) warr[w] = best;
        __syncthreads();
        if (w == 0){
            unsigned long long x = wMaxU(warr[lane]);
            if (lane == 0){
                swin = x;
                g_topidx[b*KSEL + it] = (int)(0xFFFFFFFFu - (unsigned)(x & 0xFFFFFFFFull));
            }
        }
        __syncthreads();
        unsigned long long win = swin;
        int widx = (int)(0xFFFFFFFFu - (unsigned)(win & 0xFFFFFFFFull));
        #pragma unroll
        for (int i = 0; i < 4; i++){
            int l = t + (i<<10);
            if (l == widx) v[i] = 0.f;
        }
        __syncthreads();
    }
}

// ---------------- K7: gather result rows ----------------
__global__ __launch_bounds__(128) void k_gather(float* __restrict__ outp){
    int g = blockIdx.x;
    int b = g / (BTOT*KSEL);
    int rem = g - b*(BTOT*KSEL);
    int i = rem / KSEL, k = rem - i*KSEL;
    int src = g_topidx[i*KSEL + k];
    size_t row = (size_t)(b*HWSZ + src);
    float inv = g_rowinv[row];
    const float4* s = (const float4*)&g_simE[row*NTOK];
    float4* o = (float4*)&outp[OUT_RES + (size_t)g*NTOK];
    float4 vv = s[threadIdx.x];
    vv.x *= inv; vv.y *= inv; vv.z *= inv; vv.w *= inv;
    o[threadIdx.x] = vv;
}

// ---------------- K6: conv_out GEMM (HMMA) ----------------
#define SMEM_CO 139264
__global__ __launch_bounds__(256,1) void k_conv_out(const float* __restrict__ bias,
                                                    float* __restrict__ outp){
    extern __shared__ char smem[];
    uint32_t sb = smem_u32(smem);
    int t = threadIdx.x, lane = t & 31, w = t >> 5;
    int g0 = blockIdx.x * 128;
    int b = g0 >> 12, l0 = g0 & 4095;
    int o0 = blockIdx.y * 128;

    uint32_t o_Wh = sb, o_Wl = sb + 34816, o_Dh = sb + 69632, o_Dl = sb + 104448;
    stage136(smem,          g_wouthi + (size_t)o0*DDIM, DDIM);
    stage136(smem + 34816,  g_woutlo + (size_t)o0*DDIM, DDIM);
    stage136(smem + 69632,  g_deghi + (size_t)g0*DDIM, DDIM);
    stage136(smem + 104448, g_deglo + (size_t)g0*DDIM, DDIM);
    __syncthreads();

    uint32_t aTh = o_Wh + (uint32_t)(w*16)*272u;
    uint32_t aTl = o_Wl + (uint32_t)(w*16)*272u;
    float acc[16][4] = {};
    #pragma unroll
    for (int ks = 0; ks < 8; ks++){
        uint32_t ah[4], al[4];
        ldmx4(ah, aAddr(aTh, ks*16, lane));
        ldmx4(al, aAddr(aTl, ks*16, lane));
        #pragma unroll
        for (int j = 0; j < 16; j++){
            uint32_t bh[2], bl[2];
            ldmx2(bh, bAddr(o_Dh, j*8, ks*16, lane));
            ldmx2(bl, bAddr(o_Dl, j*8, ks*16, lane));
            mma16816(acc[j], ah, bh);
            mma16816(acc[j], ah, bl);
            mma16816(acc[j], al, bh);
        }
    }
    int gid = lane >> 2, tig = lane & 3;
    int orow = o0 + w*16 + gid;
    float bb0 = bias[orow], bb1 = bias[orow + 8];
    #pragma unroll
    for (int j = 0; j < 16; j++){
        int col = l0 + j*8 + 2*tig;
        *(float2*)&outp[OUT_IMG + ((size_t)(b*CIN + orow))*HWSZ + col] =
            make_float2(acc[j][0] + bb0, acc[j][1] + bb0);
        *(float2*)&outp[OUT_IMG + ((size_t)(b*CIN + orow + 8))*HWSZ + col] =
            make_float2(acc[j][2] + bb1, acc[j][3] + bb1);
    }
}

// ---------------- launch ----------------
extern "C" void kernel_launch(void* const* d_in, const int* in_sizes, int n_in,
                              void* d_out, int out_size){
    const float* x   = (const float*)d_in[0];
    const float* DRp = (const float*)d_in[1];
    const float* ciw = (const float*)d_in[2];
    const float* cib = (const float*)d_in[3];
    const float* sw  = (const float*)d_in[4];
    const float* sb  = (const float*)d_in[5];
    const float* n1w = (const float*)d_in[6];
    const float* n1b = (const float*)d_in[7];
    const float* n2w = (const float*)d_in[8];
    const float* n2b = (const float*)d_in[9];
    const float* cow = (const float*)d_in[10];
    const float* cob = (const float*)d_in[11];
    float* out = (float*)d_out;

    cudaFuncSetAttribute(k_sem,      cudaFuncAttributeMaxDynamicSharedMemorySize, SMEM_SEM);
    cudaFuncSetAttribute(k_sim,      cudaFuncAttributeMaxDynamicSharedMemorySize, SMEM_SIM);
    cudaFuncSetAttribute(k_conv_out, cudaFuncAttributeMaxDynamicSharedMemorySize, SMEM_CO);

    k_prep_w2  <<<DDIM, 384>>>(sw, ciw, cib, sb);
    k_prep_wout<<<CIN*DDIM/256, 256>>>(cow);
    k_ln_dr    <<<NTOK, 128>>>(DRp, n2w, n2b);
    k_sem      <<<MROW/128, 256, SMEM_SEM>>>(x, n1w, n1b);
    k_sim      <<<MROW/128, 256, SMEM_SIM>>>();
    k_topk_mask<<<BTOT, 1024>>>(out);
    k_gather   <<<BTOT*BTOT*KSEL, 128>>>(out);
    k_conv_out <<<dim3(MROW/128, CIN/128), 256, SMEM_CO>>>(cob, out);
}

// round 5
// speedup vs baseline: 2.7072x; 1.0367x over previous
#include <cuda_runtime.h>
#include <cuda_bf16.h>
#include <cstdint>

#define BTOT 8
#define CIN  384
#define HWSZ 4096
#define DDIM 128
#define NTOK 512
#define MROW (BTOT*HWSZ)   // 32768
#define KSEL 81
#define LN_EPS 1e-5f

#define OUT_MASK 0
#define OUT_IMG  32768
#define OUT_RES  (32768 + BTOT*CIN*HWSZ)

// ---------------- scratch ----------------
__device__ __nv_bfloat16 g_W2hi[DDIM*CIN];            // fused conv_in∘sem weight
__device__ __nv_bfloat16 g_W2lo[DDIM*CIN];
__device__ float g_b2[DDIM];
__device__ __nv_bfloat16 g_wouthi[CIN*DDIM];
__device__ __nv_bfloat16 g_woutlo[CIN*DDIM];
__device__ __nv_bfloat16 g_drS_hi[NTOK*DDIM];         // ln(DR)[n][d]*rn[n]
__device__ __nv_bfloat16 g_drS_lo[NTOK*DDIM];
__device__ __nv_bfloat16 g_drT_hi[DDIM*NTOK];         // ln(DR) transposed [d][n]
__device__ __nv_bfloat16 g_drT_lo[DDIM*NTOK];
__device__ float g_simE[(size_t)MROW*NTOK];           // unnormalized exp(sim)
__device__ float g_rowinv[MROW];
__device__ float g_rowmax[MROW];
__device__ __nv_bfloat16 g_deghi[(size_t)MROW*DDIM];
__device__ __nv_bfloat16 g_deglo[(size_t)MROW*DDIM];
__device__ int   g_topidx[BTOT*KSEL];

// ---------------- helpers ----------------
__device__ __forceinline__ uint32_t smem_u32(const void* p){
    uint32_t a; asm("{ .reg .u64 t; cvta.to.shared.u64 t, %1; cvt.u32.u64 %0, t; }" : "=r"(a) : "l"(p));
    return a;
}
__device__ __forceinline__ void ldmx4(uint32_t* r, uint32_t addr){
    asm volatile("ldmatrix.sync.aligned.m8n8.x4.shared.b16 {%0,%1,%2,%3}, [%4];"
        : "=r"(r[0]),"=r"(r[1]),"=r"(r[2]),"=r"(r[3]) : "r"(addr));
}
__device__ __forceinline__ void ldmx4t(uint32_t* r, uint32_t addr){
    asm volatile("ldmatrix.sync.aligned.m8n8.x4.trans.shared.b16 {%0,%1,%2,%3}, [%4];"
        : "=r"(r[0]),"=r"(r[1]),"=r"(r[2]),"=r"(r[3]) : "r"(addr));
}
__device__ __forceinline__ void ldmx2(uint32_t* r, uint32_t addr){
    asm volatile("ldmatrix.sync.aligned.m8n8.x2.shared.b16 {%0,%1}, [%2];"
        : "=r"(r[0]),"=r"(r[1]) : "r"(addr));
}
__device__ __forceinline__ void mma16816(float* c, const uint32_t* a, const uint32_t* b){
    asm volatile("mma.sync.aligned.m16n8k16.row.col.f32.bf16.bf16.f32 "
        "{%0,%1,%2,%3},{%4,%5,%6,%7},{%8,%9},{%0,%1,%2,%3};"
        : "+f"(c[0]),"+f"(c[1]),"+f"(c[2]),"+f"(c[3])
        : "r"(a[0]),"r"(a[1]),"r"(a[2]),"r"(a[3]),"r"(b[0]),"r"(b[1]));
}
__device__ __forceinline__ uint32_t pack_bf2(float a, float b){
    __nv_bfloat162 t = __floats2bfloat162_rn(a,b);
    return *(uint32_t*)&t;
}
// copy a 128x128 bf16 tile (gmem row-major, stride elems) to smem rows padded to 272B
__device__ __forceinline__ void stage136(char* dst, const __nv_bfloat16* __restrict__ src, int stride){
    int t = threadIdx.x;
    #pragma unroll
    for (int i = 0; i < 8; i++){
        int idx = t + (i<<8);
        int row = idx >> 4, c8 = (idx & 15) << 3;
        *(uint4*)(dst + row*272 + c8*2) = *(const uint4*)(src + (size_t)row*stride + c8);
    }
}
// A-frag (row-major [m][k] smem rows, 272B pitch)
__device__ __forceinline__ uint32_t aAddr(uint32_t tileBase, int k0, int lane){
    return tileBase + (uint32_t)(lane & 15)*272u + (uint32_t)(k0 + ((lane>>4)<<3))*2u;
}
// A-frag via ldmatrix.trans from [k][m] smem rows (272B pitch)
__device__ __forceinline__ uint32_t aTAddr(uint32_t base, int m0, int k0, int lane){
    int row = k0 + ((lane>>4)<<3) + (lane&7);
    int col = m0 + (((lane>>3)&1)<<3);
    return base + (uint32_t)row*272u + (uint32_t)col*2u;
}
// B-frag ([n][k] rows, 272B pitch)
__device__ __forceinline__ uint32_t bAddr(uint32_t base, int n0, int k0, int lane){
    int l = lane & 15;
    return base + (uint32_t)(n0 + (l & 7))*272u + (uint32_t)(k0 + ((l>>3)&1)*8)*2u;
}
__device__ __forceinline__ float wSum(float v){
    #pragma unroll
    for (int o=16;o;o>>=1) v += __shfl_xor_sync(0xFFFFFFFFu, v, o);
    return v;
}
__device__ __forceinline__ float wMaxF(float v){
    #pragma unroll
    for (int o=16;o;o>>=1) v = fmaxf(v, __shfl_xor_sync(0xFFFFFFFFu, v, o));
    return v;
}
__device__ __forceinline__ float wMinF(float v){
    #pragma unroll
    for (int o=16;o;o>>=1) v = fminf(v, __shfl_xor_sync(0xFFFFFFFFu, v, o));
    return v;
}
__device__ __forceinline__ unsigned long long wMaxU(unsigned long long v){
    #pragma unroll
    for (int o=16;o;o>>=1){
        unsigned long long u = __shfl_xor_sync(0xFFFFFFFFu, v, o);
        if (u > v) v = u;
    }
    return v;
}
__device__ __forceinline__ float qSum(float v){
    v += __shfl_xor_sync(0xFFFFFFFFu, v, 1);
    v += __shfl_xor_sync(0xFFFFFFFFu, v, 2);
    return v;
}
__device__ __forceinline__ float qMax(float v){
    v = fmaxf(v, __shfl_xor_sync(0xFFFFFFFFu, v, 1));
    v = fmaxf(v, __shfl_xor_sync(0xFFFFFFFFu, v, 2));
    return v;
}
__device__ __forceinline__ float blockSum128(float v, float* red){
    v = wSum(v);
    int w = threadIdx.x >> 5;
    if ((threadIdx.x & 31) == 0) red[w] = v;
    __syncthreads();
    float s = red[0] + red[1] + red[2] + red[3];
    __syncthreads();
    return s;
}

// ---------------- K0a: W2 = sem_w @ conv_in_w, b2 = sem_w @ cib + semb ----------------
__global__ __launch_bounds__(384) void k_prep_w2(const float* __restrict__ sw,
                                                 const float* __restrict__ ciw,
                                                 const float* __restrict__ cib,
                                                 const float* __restrict__ semb){
    __shared__ float srow[128];
    int o = blockIdx.x, t = threadIdx.x;
    if (t < 128) srow[t] = sw[o*DDIM + t];
    __syncthreads();
    float acc = 0.f;
    #pragma unroll 4
    for (int d = 0; d < 128; d++) acc += srow[d] * ciw[d*CIN + t];
    __nv_bfloat16 h = __float2bfloat16(acc);
    g_W2hi[o*CIN + t] = h;
    g_W2lo[o*CIN + t] = __float2bfloat16(acc - __bfloat162float(h));
    if (t == 0){
        float bacc = 0.f;
        for (int d = 0; d < 128; d++) bacc += srow[d] * cib[d];
        g_b2[o] = bacc + semb[o];
    }
}
// ---------------- K0b: split Wout to bf16 hi/lo ----------------
__global__ __launch_bounds__(256) void k_prep_wout(const float* __restrict__ cow){
    int id = blockIdx.x*256 + threadIdx.x;
    float v = cow[id];
    __nv_bfloat16 h = __float2bfloat16(v);
    g_wouthi[id] = h;
    g_woutlo[id] = __float2bfloat16(v - __bfloat162float(h));
}

// ---------------- K1: layernorm of DR rows ----------------
__global__ void k_ln_dr(const float* __restrict__ DRp,
                        const float* __restrict__ w2, const float* __restrict__ b2){
    __shared__ float red[4];
    int n = blockIdx.x, t = threadIdx.x;
    float v = DRp[n*DDIM + t];
    float mean = blockSum128(v, red) * (1.f/DDIM);
    float d = v - mean;
    float var = blockSum128(d*d, red) * (1.f/DDIM);
    float rstd = rsqrtf(var + LN_EPS);
    float ln = d * rstd * w2[t] + b2[t];
    float ss = blockSum128(ln*ln, red);
    float rn = rsqrtf(ss);
    float s = ln * rn;
    __nv_bfloat16 sh = __float2bfloat16(s);
    g_drS_hi[n*DDIM + t] = sh;
    g_drS_lo[n*DDIM + t] = __float2bfloat16(s - __bfloat162float(sh));
    __nv_bfloat16 th = __float2bfloat16(ln);
    g_drT_hi[t*NTOK + n] = th;
    g_drT_lo[t*NTOK + n] = __float2bfloat16(ln - __bfloat162float(th));
}

// ========== K2: FUSED (conv_in∘sem) GEMM + double-LN + sim GEMM + softmax + degrad GEMM ==========
// smem: A/X hi|lo (2x34816) | B1 hi|lo (2x34816) | B2 hi|lo (2x34816) | consts (1536)
#define SMEM_FUSED (208896 + 1536)
__global__ __launch_bounds__(256,1) void k_fused(const float* __restrict__ x,
                                                 const float* __restrict__ n1w,
                                                 const float* __restrict__ n1b){
    extern __shared__ char smem[];
    uint32_t sb = smem_u32(smem);
    int t = threadIdx.x, lane = t & 31, w = t >> 5;
    int m0 = blockIdx.x * 128;
    int b = m0 >> 12, l0 = m0 & 4095;

    uint32_t o_Ah = sb, o_Al = sb + 34816;
    uint32_t o_B1h = sb + 69632, o_B1l = sb + 104448;
    uint32_t o_B2h = sb + 139264, o_B2l = sb + 174080;
    float* W1v = (float*)(smem + 208896);
    float* B1v = W1v + 128;
    float* b2v = B1v + 128;
    if (t < 128){ W1v[t] = n1w[t]; B1v[t] = n1b[t]; b2v[t] = g_b2[t]; }

    const float* xb = x + (size_t)b * CIN * HWSZ + l0;
    float acc[16][4] = {};

    // ===== stage A: GEMM1 out[l][d] = sum_c x[c][l] * W2[d][c], K=384 =====
    for (int ch = 0; ch < 3; ch++){
        if (ch) __syncthreads();
        // stage x chunk untransposed: smem row c (272B pitch), cols l (bf16 hi/lo)
        #pragma unroll
        for (int i = 0; i < 16; i++){
            int id = t + (i<<8);
            int cr = id >> 5;           // 0..127
            int lq = (id & 31) << 2;    // 0..124 step 4
            float4 vv = *(const float4*)(xb + (size_t)(ch*128 + cr)*HWSZ + lq);
            float hx = __bfloat162float(__float2bfloat16(vv.x));
            float hy = __bfloat162float(__float2bfloat16(vv.y));
            float hz = __bfloat162float(__float2bfloat16(vv.z));
            float hw = __bfloat162float(__float2bfloat16(vv.w));
            *(uint2*)(smem + cr*272 + lq*2) = make_uint2(pack_bf2(vv.x, vv.y), pack_bf2(vv.z, vv.w));
            *(uint2*)(smem + 34816 + cr*272 + lq*2) = make_uint2(pack_bf2(vv.x-hx, vv.y-hy), pack_bf2(vv.z-hz, vv.w-hw));
        }
        // stage W2 chunk [d][128c]
        #pragma unroll
        for (int i = 0; i < 8; i++){
            int idx = t + (i<<8);
            int row = idx >> 4, c8 = (idx & 15) << 3;
            *(uint4*)(smem + 69632  + row*272 + c8*2) = *(const uint4*)(g_W2hi + row*CIN + ch*128 + c8);
            *(uint4*)(smem + 104448 + row*272 + c8*2) = *(const uint4*)(g_W2lo + row*CIN + ch*128 + c8);
        }
        __syncthreads();
        #pragma unroll
        for (int ks = 0; ks < 8; ks++){
            uint32_t ah[4], al[4];
            ldmx4t(ah, aTAddr(o_Ah, w*16, ks*16, lane));
            ldmx4t(al, aTAddr(o_Al, w*16, ks*16, lane));
            #pragma unroll
            for (int j = 0; j < 16; j++){
                uint32_t bh[2], bl[2];
                ldmx2(bh, bAddr(o_B1h, j*8, ks*16, lane));
                ldmx2(bl, bAddr(o_B1l, j*8, ks*16, lane));
                mma16816(acc[j], ah, bh);
                mma16816(acc[j], ah, bl);
                mma16816(acc[j], al, bh);
            }
        }
    }
    __syncthreads();   // all warps done reading X before ln2 overwrites it

    // ===== double-LN epilogue -> A tile (ln2*cdlinv, bf16 hi/lo) in smem =====
    int gid = lane >> 2, tig = lane & 3;
    #pragma unroll
    for (int half = 0; half < 2; half++){
        int rl = w*16 + gid + half*8;     // block-local row
        float v[32];
        #pragma unroll
        for (int j = 0; j < 16; j++){
            int col = j*8 + 2*tig;
            v[2*j]   = acc[j][2*half]   + b2v[col];
            v[2*j+1] = acc[j][2*half+1] + b2v[col+1];
        }
        float s = 0.f;
        #pragma unroll
        for (int k = 0; k < 32; k++) s += v[k];
        float mean = qSum(s) * (1.f/DDIM);
        float q = 0.f;
        #pragma unroll
        for (int k = 0; k < 32; k++){ float d = v[k]-mean; q += d*d; }
        float rstd = rsqrtf(qSum(q)*(1.f/DDIM) + LN_EPS);
        float ln1[32]; float ss = 0.f, s2 = 0.f;
        #pragma unroll
        for (int j = 0; j < 16; j++){
            int col = j*8 + 2*tig;
            #pragma unroll
            for (int u = 0; u < 2; u++){
                float y = (v[2*j+u]-mean)*rstd*W1v[col+u] + B1v[col+u];
                ln1[2*j+u] = y; ss += y*y; s2 += y;
            }
        }
        float cdlinv = rsqrtf(qSum(ss));
        float m2 = qSum(s2) * (1.f/DDIM);
        float q2 = 0.f;
        #pragma unroll
        for (int k = 0; k < 32; k++){ float d = ln1[k]-m2; q2 += d*d; }
        float rstd2 = rsqrtf(qSum(q2)*(1.f/DDIM) + LN_EPS);
        #pragma unroll
        for (int j = 0; j < 16; j++){
            int col = j*8 + 2*tig;
            float y0 = ((ln1[2*j]-m2)*rstd2*W1v[col] + B1v[col]) * cdlinv;
            float y1 = ((ln1[2*j+1]-m2)*rstd2*W1v[col+1] + B1v[col+1]) * cdlinv;
            float h0 = __bfloat162float(__float2bfloat16(y0));
            float h1 = __bfloat162float(__float2bfloat16(y1));
            *(uint32_t*)(smem + rl*272 + col*2) = pack_bf2(y0, y1);
            *(uint32_t*)(smem + 34816 + rl*272 + col*2) = pack_bf2(y0-h0, y1-h1);
        }
    }

    // ===== phase 2: sim GEMM + softmax + degrad GEMM =====
    uint32_t aTh = o_Ah + (uint32_t)(w*16)*272u;
    uint32_t aTl = o_Al + (uint32_t)(w*16)*272u;
    int rlo = m0 + w*16 + gid, rhi = rlo + 8;

    float acc2[16][4] = {};
    float sum_lo = 0.f, sum_hi = 0.f, emax_lo = 0.f, emax_hi = 0.f;

    for (int c = 0; c < 4; c++){
        __syncthreads();
        stage136(smem + 69632,  g_drS_hi + (size_t)c*128*DDIM, DDIM);
        stage136(smem + 104448, g_drS_lo + (size_t)c*128*DDIM, DDIM);
        stage136(smem + 139264, g_drT_hi + c*128, NTOK);
        stage136(smem + 174080, g_drT_lo + c*128, NTOK);
        __syncthreads();

        float acc1[16][4] = {};
        #pragma unroll
        for (int ks = 0; ks < 8; ks++){
            uint32_t ah[4], al[4];
            ldmx4(ah, aAddr(aTh, ks*16, lane));
            ldmx4(al, aAddr(aTl, ks*16, lane));
            #pragma unroll
            for (int j = 0; j < 16; j++){
                uint32_t bh[2], bl[2];
                ldmx2(bh, bAddr(o_B1h, j*8, ks*16, lane));
                ldmx2(bl, bAddr(o_B1l, j*8, ks*16, lane));
                mma16816(acc1[j], ah, bh);
                mma16816(acc1[j], ah, bl);
                mma16816(acc1[j], al, bh);
            }
        }

        uint32_t ehi[16][2], elo[16][2];
        #pragma unroll
        for (int j = 0; j < 16; j++){
            float e0 = __expf(acc1[j][0]), e1 = __expf(acc1[j][1]);
            float e2 = __expf(acc1[j][2]), e3 = __expf(acc1[j][3]);
            sum_lo += e0 + e1; sum_hi += e2 + e3;
            emax_lo = fmaxf(emax_lo, fmaxf(e0, e1));
            emax_hi = fmaxf(emax_hi, fmaxf(e2, e3));
            int col = c*128 + j*8 + 2*tig;
            *(float2*)&g_simE[(size_t)rlo*NTOK + col] = make_float2(e0, e1);
            *(float2*)&g_simE[(size_t)rhi*NTOK + col] = make_float2(e2, e3);
            float h0 = __bfloat162float(__float2bfloat16(e0));
            float h1 = __bfloat162float(__float2bfloat16(e1));
            float h2 = __bfloat162float(__float2bfloat16(e2));
            float h3 = __bfloat162float(__float2bfloat16(e3));
            ehi[j][0] = pack_bf2(e0, e1);      ehi[j][1] = pack_bf2(e2, e3);
            elo[j][0] = pack_bf2(e0-h0, e1-h1); elo[j][1] = pack_bf2(e2-h2, e3-h3);
        }

        #pragma unroll
        for (int k = 0; k < 8; k++){
            uint32_t ah[4] = { ehi[2*k][0], ehi[2*k][1], ehi[2*k+1][0], ehi[2*k+1][1] };
            uint32_t al[4] = { elo[2*k][0], elo[2*k][1], elo[2*k+1][0], elo[2*k+1][1] };
            #pragma unroll
            for (int j2 = 0; j2 < 16; j2++){
                uint32_t bh[2], bl[2];
                ldmx2(bh, bAddr(o_B2h, j2*8, k*16, lane));
                ldmx2(bl, bAddr(o_B2l, j2*8, k*16, lane));
                mma16816(acc2[j2], ah, bh);
                mma16816(acc2[j2], ah, bl);
                mma16816(acc2[j2], al, bh);
            }
        }
    }

    sum_lo = qSum(sum_lo); sum_hi = qSum(sum_hi);
    emax_lo = qMax(emax_lo); emax_hi = qMax(emax_hi);
    float inv_lo = 1.f / sum_lo, inv_hi = 1.f / sum_hi;
    if (tig == 0){
        g_rowinv[rlo] = inv_lo;  g_rowinv[rhi] = inv_hi;
        g_rowmax[rlo] = emax_lo * inv_lo;  g_rowmax[rhi] = emax_hi * inv_hi;
    }
    #pragma unroll
    for (int j2 = 0; j2 < 16; j2++){
        int dcol = j2*8 + 2*tig;
        float y0 = acc2[j2][0]*inv_lo, y1 = acc2[j2][1]*inv_lo;
        float y2 = acc2[j2][2]*inv_hi, y3 = acc2[j2][3]*inv_hi;
        float h0 = __bfloat162float(__float2bfloat16(y0));
        float h1 = __bfloat162float(__float2bfloat16(y1));
        float h2 = __bfloat162float(__float2bfloat16(y2));
        float h3 = __bfloat162float(__float2bfloat16(y3));
        *(uint32_t*)&g_deghi[(size_t)rlo*DDIM + dcol] = pack_bf2(y0, y1);
        *(uint32_t*)&g_deglo[(size_t)rlo*DDIM + dcol] = pack_bf2(y0-h0, y1-h1);
        *(uint32_t*)&g_deghi[(size_t)rhi*DDIM + dcol] = pack_bf2(y2, y3);
        *(uint32_t*)&g_deglo[(size_t)rhi*DDIM + dcol] = pack_bf2(y2-h2, y3-h3);
    }
}

// ---------------- K5: mask + top-81 ----------------
__global__ __launch_bounds__(1024) void k_topk_mask(float* __restrict__ outp){
    __shared__ unsigned long long warr[32];
    __shared__ unsigned long long swin;
    __shared__ float sred[32];
    __shared__ float s_mn, s_mx;
    int b = blockIdx.x, t = threadIdx.x;
    int lane = t & 31, w = t >> 5;
    float v[4];
    float mn = 1e30f, mx = -1e30f;
    #pragma unroll
    for (int i = 0; i < 4; i++){
        v[i] = g_rowmax[b*HWSZ + t + (i<<10)];
        mn = fminf(mn, v[i]); mx = fmaxf(mx, v[i]);
    }
    mn = wMinF(mn);
    if (lane == 0) sred[w] = mn;
    __syncthreads();
    if (w == 0){ float x = wMinF(sred[lane]); if (lane == 0) s_mn = x; }
    __syncthreads();
    mx = wMaxF(mx);
    if (lane == 0) sred[w] = mx;
    __syncthreads();
    if (w == 0){ float x = wMaxF(sred[lane]); if (lane == 0) s_mx = x; }
    __syncthreads();
    float mn3 = s_mn*s_mn*s_mn, mx3 = s_mx*s_mx*s_mx;
    float inv = 1.f / (mx3 - mn3);
    #pragma unroll
    for (int i = 0; i < 4; i++){
        int l = t + (i<<10);
        outp[OUT_MASK + b*HWSZ + l] = 1.f - (v[i]*v[i]*v[i] - mn3) * inv;
    }
    for (int it = 0; it < KSEL; it++){
        unsigned long long best = 0ull;
        #pragma unroll
        for (int i = 0; i < 4; i++){
            int l = t + (i<<10);
            unsigned long long key =
                ((unsigned long long)__float_as_uint(v[i]) << 32) | (unsigned)(0xFFFFFFFFu - (unsigned)l);
            if (key > best) best = key;
        }
        best = wMaxU(best);
        if (lane == 0) warr[w] = best;
        __syncthreads();
        if (w == 0){
            unsigned long long x = wMaxU(warr[lane]);
            if (lane == 0){
                swin = x;
                g_topidx[b*KSEL + it] = (int)(0xFFFFFFFFu - (unsigned)(x & 0xFFFFFFFFull));
            }
        }
        __syncthreads();
        unsigned long long win = swin;
        int widx = (int)(0xFFFFFFFFu - (unsigned)(win & 0xFFFFFFFFull));
        #pragma unroll
        for (int i = 0; i < 4; i++){
            int l = t + (i<<10);
            if (l == widx) v[i] = 0.f;
        }
        __syncthreads();
    }
}

// ---------------- K7: gather result rows ----------------
__global__ __launch_bounds__(128) void k_gather(float* __restrict__ outp){
    int g = blockIdx.x;
    int b = g / (BTOT*KSEL);
    int rem = g - b*(BTOT*KSEL);
    int i = rem / KSEL, k = rem - i*KSEL;
    int src = g_topidx[i*KSEL + k];
    size_t row = (size_t)(b*HWSZ + src);
    float inv = g_rowinv[row];
    const float4* s = (const float4*)&g_simE[row*NTOK];
    float4* o = (float4*)&outp[OUT_RES + (size_t)g*NTOK];
    float4 vv = s[threadIdx.x];
    vv.x *= inv; vv.y *= inv; vv.z *= inv; vv.w *= inv;
    o[threadIdx.x] = vv;
}

// ---------------- K6: conv_out GEMM (HMMA) ----------------
#define SMEM_CO 139264
__global__ __launch_bounds__(256,1) void k_conv_out(const float* __restrict__ bias,
                                                    float* __restrict__ outp){
    extern __shared__ char smem[];
    uint32_t sb = smem_u32(smem);
    int t = threadIdx.x, lane = t & 31, w = t >> 5;
    int g0 = blockIdx.x * 128;
    int b = g0 >> 12, l0 = g0 & 4095;
    int o0 = blockIdx.y * 128;

    uint32_t o_Wh = sb, o_Wl = sb + 34816, o_Dh = sb + 69632, o_Dl = sb + 104448;
    stage136(smem,          g_wouthi + (size_t)o0*DDIM, DDIM);
    stage136(smem + 34816,  g_woutlo + (size_t)o0*DDIM, DDIM);
    stage136(smem + 69632,  g_deghi + (size_t)g0*DDIM, DDIM);
    stage136(smem + 104448, g_deglo + (size_t)g0*DDIM, DDIM);
    __syncthreads();

    uint32_t aTh = o_Wh + (uint32_t)(w*16)*272u;
    uint32_t aTl = o_Wl + (uint32_t)(w*16)*272u;
    float acc[16][4] = {};
    #pragma unroll
    for (int ks = 0; ks < 8; ks++){
        uint32_t ah[4], al[4];
        ldmx4(ah, aAddr(aTh, ks*16, lane));
        ldmx4(al, aAddr(aTl, ks*16, lane));
        #pragma unroll
        for (int j = 0; j < 16; j++){
            uint32_t bh[2], bl[2];
            ldmx2(bh, bAddr(o_Dh, j*8, ks*16, lane));
            ldmx2(bl, bAddr(o_Dl, j*8, ks*16, lane));
            mma16816(acc[j], ah, bh);
            mma16816(acc[j], ah, bl);
            mma16816(acc[j], al, bh);
        }
    }
    int gid = lane >> 2, tig = lane & 3;
    int orow = o0 + w*16 + gid;
    float bb0 = bias[orow], bb1 = bias[orow + 8];
    #pragma unroll
    for (int j = 0; j < 16; j++){
        int col = l0 + j*8 + 2*tig;
        *(float2*)&outp[OUT_IMG + ((size_t)(b*CIN + orow))*HWSZ + col] =
            make_float2(acc[j][0] + bb0, acc[j][1] + bb0);
        *(float2*)&outp[OUT_IMG + ((size_t)(b*CIN + orow + 8))*HWSZ + col] =
            make_float2(acc[j][2] + bb1, acc[j][3] + bb1);
    }
}

// ---------------- launch ----------------
extern "C" void kernel_launch(void* const* d_in, const int* in_sizes, int n_in,
                              void* d_out, int out_size){
    const float* x   = (const float*)d_in[0];
    const float* DRp = (const float*)d_in[1];
    const float* ciw = (const float*)d_in[2];
    const float* cib = (const float*)d_in[3];
    const float* sw  = (const float*)d_in[4];
    const float* sb  = (const float*)d_in[5];
    const float* n1w = (const float*)d_in[6];
    const float* n1b = (const float*)d_in[7];
    const float* n2w = (const float*)d_in[8];
    const float* n2b = (const float*)d_in[9];
    const float* cow = (const float*)d_in[10];
    const float* cob = (const float*)d_in[11];
    float* out = (float*)d_out;

    cudaFuncSetAttribute(k_fused,    cudaFuncAttributeMaxDynamicSharedMemorySize, SMEM_FUSED);
    cudaFuncSetAttribute(k_conv_out, cudaFuncAttributeMaxDynamicSharedMemorySize, SMEM_CO);

    k_prep_w2  <<<DDIM, 384>>>(sw, ciw, cib, sb);
    k_prep_wout<<<CIN*DDIM/256, 256>>>(cow);
    k_ln_dr    <<<NTOK, 128>>>(DRp, n2w, n2b);
    k_fused    <<<MROW/128, 256, SMEM_FUSED>>>(x, n1w, n1b);
    k_topk_mask<<<BTOT, 1024>>>(out);
    k_gather   <<<BTOT*BTOT*KSEL, 128>>>(out);
    k_conv_out <<<dim3(MROW/128, CIN/128), 256, SMEM_CO>>>(cob, out);
}

// round 6
// speedup vs baseline: 2.9121x; 1.0757x over previous
#include <cuda_runtime.h>
#include <cuda_bf16.h>
#include <cstdint>

#define BTOT 8
#define CIN  384
#define HWSZ 4096
#define DDIM 128
#define NTOK 512
#define MROW (BTOT*HWSZ)   // 32768
#define KSEL 81
#define LN_EPS 1e-5f

#define OUT_MASK 0
#define OUT_IMG  32768
#define OUT_RES  (32768 + BTOT*CIN*HWSZ)

// ---------------- scratch ----------------
__device__ __nv_bfloat16 g_W2hi[DDIM*CIN];            // fused conv_in∘sem weight
__device__ __nv_bfloat16 g_W2lo[DDIM*CIN];
__device__ float g_b2[DDIM];
__device__ __nv_bfloat16 g_wouthi[CIN*DDIM];
__device__ __nv_bfloat16 g_woutlo[CIN*DDIM];
__device__ __nv_bfloat16 g_dr_hi[NTOK*DDIM];          // ln(DR)[n][d] plain
__device__ __nv_bfloat16 g_dr_lo[NTOK*DDIM];
__device__ float g_rn[NTOK];                          // 1/||ln(DR)[n]||
__device__ float g_simE[(size_t)MROW*NTOK];           // unnormalized exp(sim)
__device__ float g_rowinv[MROW];
__device__ float g_rowmax[MROW];
__device__ int   g_topidx[BTOT*KSEL];

// ---------------- helpers ----------------
__device__ __forceinline__ uint32_t smem_u32(const void* p){
    uint32_t a; asm("{ .reg .u64 t; cvta.to.shared.u64 t, %1; cvt.u32.u64 %0, t; }" : "=r"(a) : "l"(p));
    return a;
}
__device__ __forceinline__ void ldmx4(uint32_t* r, uint32_t addr){
    asm volatile("ldmatrix.sync.aligned.m8n8.x4.shared.b16 {%0,%1,%2,%3}, [%4];"
        : "=r"(r[0]),"=r"(r[1]),"=r"(r[2]),"=r"(r[3]) : "r"(addr));
}
__device__ __forceinline__ void ldmx4t(uint32_t* r, uint32_t addr){
    asm volatile("ldmatrix.sync.aligned.m8n8.x4.trans.shared.b16 {%0,%1,%2,%3}, [%4];"
        : "=r"(r[0]),"=r"(r[1]),"=r"(r[2]),"=r"(r[3]) : "r"(addr));
}
__device__ __forceinline__ void ldmx2(uint32_t* r, uint32_t addr){
    asm volatile("ldmatrix.sync.aligned.m8n8.x2.shared.b16 {%0,%1}, [%2];"
        : "=r"(r[0]),"=r"(r[1]) : "r"(addr));
}
__device__ __forceinline__ void ldmx2t(uint32_t* r, uint32_t addr){
    asm volatile("ldmatrix.sync.aligned.m8n8.x2.trans.shared.b16 {%0,%1}, [%2];"
        : "=r"(r[0]),"=r"(r[1]) : "r"(addr));
}
__device__ __forceinline__ void mma16816(float* c, const uint32_t* a, const uint32_t* b){
    asm volatile("mma.sync.aligned.m16n8k16.row.col.f32.bf16.bf16.f32 "
        "{%0,%1,%2,%3},{%4,%5,%6,%7},{%8,%9},{%0,%1,%2,%3};"
        : "+f"(c[0]),"+f"(c[1]),"+f"(c[2]),"+f"(c[3])
        : "r"(a[0]),"r"(a[1]),"r"(a[2]),"r"(a[3]),"r"(b[0]),"r"(b[1]));
}
__device__ __forceinline__ uint32_t pack_bf2(float a, float b){
    __nv_bfloat162 t = __floats2bfloat162_rn(a,b);
    return *(uint32_t*)&t;
}
// copy a 128x128 bf16 tile (gmem row-major, stride elems) to smem rows padded to 272B
__device__ __forceinline__ void stage136(char* dst, const __nv_bfloat16* __restrict__ src, int stride){
    int t = threadIdx.x;
    #pragma unroll
    for (int i = 0; i < 8; i++){
        int idx = t + (i<<8);
        int row = idx >> 4, c8 = (idx & 15) << 3;
        *(uint4*)(dst + row*272 + c8*2) = *(const uint4*)(src + (size_t)row*stride + c8);
    }
}
// A-frag (row-major [m][k] smem rows, 272B pitch)
__device__ __forceinline__ uint32_t aAddr(uint32_t tileBase, int k0, int lane){
    return tileBase + (uint32_t)(lane & 15)*272u + (uint32_t)(k0 + ((lane>>4)<<3))*2u;
}
// A-frag via ldmatrix.trans from [k][m] smem rows
__device__ __forceinline__ uint32_t aTAddr(uint32_t base, int m0, int k0, int lane){
    int row = k0 + ((lane>>4)<<3) + (lane&7);
    int col = m0 + (((lane>>3)&1)<<3);
    return base + (uint32_t)row*272u + (uint32_t)col*2u;
}
// B-frag ([n][k] rows)
__device__ __forceinline__ uint32_t bAddr(uint32_t base, int n0, int k0, int lane){
    int l = lane & 15;
    return base + (uint32_t)(n0 + (l & 7))*272u + (uint32_t)(k0 + ((l>>3)&1)*8)*2u;
}
// B-frag via trans from [k][n] rows (source row=k, col=n)
__device__ __forceinline__ uint32_t bTAddr(uint32_t base, int n0, int k0, int lane){
    return base + (uint32_t)(k0 + (lane & 15))*272u + (uint32_t)n0*2u;
}
__device__ __forceinline__ float wSum(float v){
    #pragma unroll
    for (int o=16;o;o>>=1) v += __shfl_xor_sync(0xFFFFFFFFu, v, o);
    return v;
}
__device__ __forceinline__ float wMaxF(float v){
    #pragma unroll
    for (int o=16;o;o>>=1) v = fmaxf(v, __shfl_xor_sync(0xFFFFFFFFu, v, o));
    return v;
}
__device__ __forceinline__ float wMinF(float v){
    #pragma unroll
    for (int o=16;o;o>>=1) v = fminf(v, __shfl_xor_sync(0xFFFFFFFFu, v, o));
    return v;
}
__device__ __forceinline__ unsigned long long wMaxU(unsigned long long v){
    #pragma unroll
    for (int o=16;o;o>>=1){
        unsigned long long u = __shfl_xor_sync(0xFFFFFFFFu, v, o);
        if (u > v) v = u;
    }
    return v;
}
__device__ __forceinline__ float qSum(float v){
    v += __shfl_xor_sync(0xFFFFFFFFu, v, 1);
    v += __shfl_xor_sync(0xFFFFFFFFu, v, 2);
    return v;
}
__device__ __forceinline__ float qMax(float v){
    v = fmaxf(v, __shfl_xor_sync(0xFFFFFFFFu, v, 1));
    v = fmaxf(v, __shfl_xor_sync(0xFFFFFFFFu, v, 2));
    return v;
}
__device__ __forceinline__ float blockSum128(float v, float* red){
    v = wSum(v);
    int w = threadIdx.x >> 5;
    if ((threadIdx.x & 31) == 0) red[w] = v;
    __syncthreads();
    float s = red[0] + red[1] + red[2] + red[3];
    __syncthreads();
    return s;
}

// ---------------- K0a: W2 = sem_w @ conv_in_w, b2 ----------------
__global__ __launch_bounds__(384) void k_prep_w2(const float* __restrict__ sw,
                                                 const float* __restrict__ ciw,
                                                 const float* __restrict__ cib,
                                                 const float* __restrict__ semb){
    __shared__ float srow[128];
    int o = blockIdx.x, t = threadIdx.x;
    if (t < 128) srow[t] = sw[o*DDIM + t];
    __syncthreads();
    float acc = 0.f;
    #pragma unroll 4
    for (int d = 0; d < 128; d++) acc += srow[d] * ciw[d*CIN + t];
    __nv_bfloat16 h = __float2bfloat16(acc);
    g_W2hi[o*CIN + t] = h;
    g_W2lo[o*CIN + t] = __float2bfloat16(acc - __bfloat162float(h));
    if (t == 0){
        float bacc = 0.f;
        for (int d = 0; d < 128; d++) bacc += srow[d] * cib[d];
        g_b2[o] = bacc + semb[o];
    }
}
// ---------------- K0b: split Wout ----------------
__global__ __launch_bounds__(256) void k_prep_wout(const float* __restrict__ cow){
    int id = blockIdx.x*256 + threadIdx.x;
    float v = cow[id];
    __nv_bfloat16 h = __float2bfloat16(v);
    g_wouthi[id] = h;
    g_woutlo[id] = __float2bfloat16(v - __bfloat162float(h));
}

// ---------------- K1: layernorm of DR rows ----------------
__global__ void k_ln_dr(const float* __restrict__ DRp,
                        const float* __restrict__ w2, const float* __restrict__ b2){
    __shared__ float red[4];
    int n = blockIdx.x, t = threadIdx.x;
    float v = DRp[n*DDIM + t];
    float mean = blockSum128(v, red) * (1.f/DDIM);
    float d = v - mean;
    float var = blockSum128(d*d, red) * (1.f/DDIM);
    float rstd = rsqrtf(var + LN_EPS);
    float ln = d * rstd * w2[t] + b2[t];
    float ss = blockSum128(ln*ln, red);
    __nv_bfloat16 h = __float2bfloat16(ln);
    g_dr_hi[n*DDIM + t] = h;
    g_dr_lo[n*DDIM + t] = __float2bfloat16(ln - __bfloat162float(h));
    if (t == 0) g_rn[n] = rsqrtf(ss);
}

// ========== K2: FUSED sem GEMM + double-LN + sim + softmax + degrad + conv_out ==========
// smem: A hi|lo (2x34816) | B hi|lo (2x34816) | consts: W1,B1,b2 (3x512B) + rn (2048B)
#define SMEM_FUSED (139264 + 3584)
__global__ __launch_bounds__(256,1) void k_fused(const float* __restrict__ x,
                                                 const float* __restrict__ n1w,
                                                 const float* __restrict__ n1b,
                                                 const float* __restrict__ cob,
                                                 float* __restrict__ outp){
    extern __shared__ char smem[];
    uint32_t sb = smem_u32(smem);
    int t = threadIdx.x, lane = t & 31, w = t >> 5;
    int m0 = blockIdx.x * 128;
    int b = m0 >> 12, l0 = m0 & 4095;

    uint32_t o_Ah = sb, o_Al = sb + 34816;
    uint32_t o_Bh = sb + 69632, o_Bl = sb + 104448;
    float* W1v = (float*)(smem + 139264);
    float* B1v = W1v + 128;
    float* b2v = B1v + 128;
    float* rnv = b2v + 128;
    if (t < 128){ W1v[t] = n1w[t]; B1v[t] = n1b[t]; b2v[t] = g_b2[t]; }
    rnv[t] = g_rn[t]; rnv[t+256] = g_rn[t+256];

    const float* xb = x + (size_t)b * CIN * HWSZ + l0;
    float acc[16][4] = {};

    // ===== phase 1: GEMM1 out[l][d] = sum_c x[c][l]*W2[d][c], K=384 =====
    for (int ch = 0; ch < 3; ch++){
        if (ch) __syncthreads();
        #pragma unroll
        for (int i = 0; i < 16; i++){
            int id = t + (i<<8);
            int cr = id >> 5;
            int lq = (id & 31) << 2;
            float4 vv = *(const float4*)(xb + (size_t)(ch*128 + cr)*HWSZ + lq);
            float hx = __bfloat162float(__float2bfloat16(vv.x));
            float hy = __bfloat162float(__float2bfloat16(vv.y));
            float hz = __bfloat162float(__float2bfloat16(vv.z));
            float hw = __bfloat162float(__float2bfloat16(vv.w));
            *(uint2*)(smem + cr*272 + lq*2) = make_uint2(pack_bf2(vv.x, vv.y), pack_bf2(vv.z, vv.w));
            *(uint2*)(smem + 34816 + cr*272 + lq*2) = make_uint2(pack_bf2(vv.x-hx, vv.y-hy), pack_bf2(vv.z-hz, vv.w-hw));
        }
        #pragma unroll
        for (int i = 0; i < 8; i++){
            int idx = t + (i<<8);
            int row = idx >> 4, c8 = (idx & 15) << 3;
            *(uint4*)(smem + 69632  + row*272 + c8*2) = *(const uint4*)(g_W2hi + row*CIN + ch*128 + c8);
            *(uint4*)(smem + 104448 + row*272 + c8*2) = *(const uint4*)(g_W2lo + row*CIN + ch*128 + c8);
        }
        __syncthreads();
        #pragma unroll
        for (int ks = 0; ks < 8; ks++){
            uint32_t ah[4], al[4];
            ldmx4t(ah, aTAddr(o_Ah, w*16, ks*16, lane));
            ldmx4t(al, aTAddr(o_Al, w*16, ks*16, lane));
            #pragma unroll
            for (int j = 0; j < 16; j++){
                uint32_t bh[2], bl[2];
                ldmx2(bh, bAddr(o_Bh, j*8, ks*16, lane));
                ldmx2(bl, bAddr(o_Bl, j*8, ks*16, lane));
                mma16816(acc[j], ah, bh);
                mma16816(acc[j], ah, bl);
                mma16816(acc[j], al, bh);
            }
        }
    }
    __syncthreads();

    // ===== double-LN epilogue -> A tile (ln2*cdlinv bf16 hi/lo) =====
    int gid = lane >> 2, tig = lane & 3;
    #pragma unroll
    for (int half = 0; half < 2; half++){
        int rl = w*16 + gid + half*8;
        float v[32];
        #pragma unroll
        for (int j = 0; j < 16; j++){
            int col = j*8 + 2*tig;
            v[2*j]   = acc[j][2*half]   + b2v[col];
            v[2*j+1] = acc[j][2*half+1] + b2v[col+1];
        }
        float s = 0.f;
        #pragma unroll
        for (int k = 0; k < 32; k++) s += v[k];
        float mean = qSum(s) * (1.f/DDIM);
        float q = 0.f;
        #pragma unroll
        for (int k = 0; k < 32; k++){ float d = v[k]-mean; q += d*d; }
        float rstd = rsqrtf(qSum(q)*(1.f/DDIM) + LN_EPS);
        float ln1[32]; float ss = 0.f, s2 = 0.f;
        #pragma unroll
        for (int j = 0; j < 16; j++){
            int col = j*8 + 2*tig;
            #pragma unroll
            for (int u = 0; u < 2; u++){
                float y = (v[2*j+u]-mean)*rstd*W1v[col+u] + B1v[col+u];
                ln1[2*j+u] = y; ss += y*y; s2 += y;
            }
        }
        float cdlinv = rsqrtf(qSum(ss));
        float m2 = qSum(s2) * (1.f/DDIM);
        float q2 = 0.f;
        #pragma unroll
        for (int k = 0; k < 32; k++){ float d = ln1[k]-m2; q2 += d*d; }
        float rstd2 = rsqrtf(qSum(q2)*(1.f/DDIM) + LN_EPS);
        #pragma unroll
        for (int j = 0; j < 16; j++){
            int col = j*8 + 2*tig;
            float y0 = ((ln1[2*j]-m2)*rstd2*W1v[col] + B1v[col]) * cdlinv;
            float y1 = ((ln1[2*j+1]-m2)*rstd2*W1v[col+1] + B1v[col+1]) * cdlinv;
            float h0 = __bfloat162float(__float2bfloat16(y0));
            float h1 = __bfloat162float(__float2bfloat16(y1));
            *(uint32_t*)(smem + rl*272 + col*2) = pack_bf2(y0, y1);
            *(uint32_t*)(smem + 34816 + rl*272 + col*2) = pack_bf2(y0-h0, y1-h1);
        }
    }

    // ===== phase 2: sim + softmax + degrad (dr tile shared by MMA1 & MMA2-trans) =====
    uint32_t aTh = o_Ah + (uint32_t)(w*16)*272u;
    uint32_t aTl = o_Al + (uint32_t)(w*16)*272u;
    int rlo = m0 + w*16 + gid, rhi = rlo + 8;

    float acc2[16][4] = {};
    float sum_lo = 0.f, sum_hi = 0.f, emax_lo = 0.f, emax_hi = 0.f;

    for (int c = 0; c < 4; c++){
        __syncthreads();
        stage136(smem + 69632,  g_dr_hi + (size_t)c*128*DDIM, DDIM);
        stage136(smem + 104448, g_dr_lo + (size_t)c*128*DDIM, DDIM);
        __syncthreads();

        float acc1[16][4] = {};
        #pragma unroll
        for (int ks = 0; ks < 8; ks++){
            uint32_t ah[4], al[4];
            ldmx4(ah, aAddr(aTh, ks*16, lane));
            ldmx4(al, aAddr(aTl, ks*16, lane));
            #pragma unroll
            for (int j = 0; j < 16; j++){
                uint32_t bh[2], bl[2];
                ldmx2(bh, bAddr(o_Bh, j*8, ks*16, lane));
                ldmx2(bl, bAddr(o_Bl, j*8, ks*16, lane));
                mma16816(acc1[j], ah, bh);
                mma16816(acc1[j], ah, bl);
                mma16816(acc1[j], al, bh);
            }
        }

        uint32_t ehi[16][2], elo[16][2];
        #pragma unroll
        for (int j = 0; j < 16; j++){
            int coll = j*8 + 2*tig;
            float rn0 = rnv[c*128 + coll], rn1 = rnv[c*128 + coll + 1];
            float e0 = __expf(acc1[j][0]*rn0), e1 = __expf(acc1[j][1]*rn1);
            float e2 = __expf(acc1[j][2]*rn0), e3 = __expf(acc1[j][3]*rn1);
            sum_lo += e0 + e1; sum_hi += e2 + e3;
            emax_lo = fmaxf(emax_lo, fmaxf(e0, e1));
            emax_hi = fmaxf(emax_hi, fmaxf(e2, e3));
            int col = c*128 + coll;
            *(float2*)&g_simE[(size_t)rlo*NTOK + col] = make_float2(e0, e1);
            *(float2*)&g_simE[(size_t)rhi*NTOK + col] = make_float2(e2, e3);
            float h0 = __bfloat162float(__float2bfloat16(e0));
            float h1 = __bfloat162float(__float2bfloat16(e1));
            float h2 = __bfloat162float(__float2bfloat16(e2));
            float h3 = __bfloat162float(__float2bfloat16(e3));
            ehi[j][0] = pack_bf2(e0, e1);      ehi[j][1] = pack_bf2(e2, e3);
            elo[j][0] = pack_bf2(e0-h0, e1-h1); elo[j][1] = pack_bf2(e2-h2, e3-h3);
        }

        #pragma unroll
        for (int k = 0; k < 8; k++){
            uint32_t ah[4] = { ehi[2*k][0], ehi[2*k][1], ehi[2*k+1][0], ehi[2*k+1][1] };
            uint32_t al[4] = { elo[2*k][0], elo[2*k][1], elo[2*k+1][0], elo[2*k+1][1] };
            #pragma unroll
            for (int j2 = 0; j2 < 16; j2++){
                uint32_t bh[2], bl[2];
                ldmx2t(bh, bTAddr(o_Bh, j2*8, k*16, lane));
                ldmx2t(bl, bTAddr(o_Bl, j2*8, k*16, lane));
                mma16816(acc2[j2], ah, bh);
                mma16816(acc2[j2], ah, bl);
                mma16816(acc2[j2], al, bh);
            }
        }
    }

    sum_lo = qSum(sum_lo); sum_hi = qSum(sum_hi);
    emax_lo = qMax(emax_lo); emax_hi = qMax(emax_hi);
    float inv_lo = 1.f / sum_lo, inv_hi = 1.f / sum_hi;
    if (tig == 0){
        g_rowinv[rlo] = inv_lo;  g_rowinv[rhi] = inv_hi;
        g_rowmax[rlo] = emax_lo * inv_lo;  g_rowmax[rhi] = emax_hi * inv_hi;
    }
    __syncthreads();   // done reading A (ln2) and B (dr) tiles

    // write degrad bf16 hi/lo into A slots: rows = local pixel, cols = d
    #pragma unroll
    for (int j2 = 0; j2 < 16; j2++){
        int dcol = j2*8 + 2*tig;
        int rl_lo = w*16 + gid, rl_hi = rl_lo + 8;
        float y0 = acc2[j2][0]*inv_lo, y1 = acc2[j2][1]*inv_lo;
        float y2 = acc2[j2][2]*inv_hi, y3 = acc2[j2][3]*inv_hi;
        float h0 = __bfloat162float(__float2bfloat16(y0));
        float h1 = __bfloat162float(__float2bfloat16(y1));
        float h2 = __bfloat162float(__float2bfloat16(y2));
        float h3 = __bfloat162float(__float2bfloat16(y3));
        *(uint32_t*)(smem + rl_lo*272 + dcol*2) = pack_bf2(y0, y1);
        *(uint32_t*)(smem + 34816 + rl_lo*272 + dcol*2) = pack_bf2(y0-h0, y1-h1);
        *(uint32_t*)(smem + rl_hi*272 + dcol*2) = pack_bf2(y2, y3);
        *(uint32_t*)(smem + 34816 + rl_hi*272 + dcol*2) = pack_bf2(y2-h2, y3-h3);
    }

    // ===== phase 3: conv_out  out[o][l] = sum_d wout[o][d]*degrad[l][d] =====
    for (int co = 0; co < 3; co++){
        __syncthreads();
        stage136(smem + 69632,  g_wouthi + (size_t)(co*128)*DDIM, DDIM);
        stage136(smem + 104448, g_woutlo + (size_t)(co*128)*DDIM, DDIM);
        __syncthreads();
        float acc3[16][4] = {};
        #pragma unroll
        for (int ks = 0; ks < 8; ks++){
            uint32_t ah[4], al[4];
            ldmx4(ah, aAddr(o_Bh + (uint32_t)(w*16)*272u, ks*16, lane));   // A = wout [o][d]
            ldmx4(al, aAddr(o_Bl + (uint32_t)(w*16)*272u, ks*16, lane));
            #pragma unroll
            for (int j = 0; j < 16; j++){
                uint32_t bh[2], bl[2];
                ldmx2(bh, bAddr(o_Ah, j*8, ks*16, lane));                  // B = degrad [l][d]
                ldmx2(bl, bAddr(o_Al, j*8, ks*16, lane));
                mma16816(acc3[j], ah, bh);
                mma16816(acc3[j], ah, bl);
                mma16816(acc3[j], al, bh);
            }
        }
        int orow = co*128 + w*16 + gid;
        float bb0 = __ldg(cob + orow), bb1 = __ldg(cob + orow + 8);
        #pragma unroll
        for (int j = 0; j < 16; j++){
            int col = l0 + j*8 + 2*tig;
            *(float2*)&outp[OUT_IMG + ((size_t)(b*CIN + orow))*HWSZ + col] =
                make_float2(acc3[j][0] + bb0, acc3[j][1] + bb0);
            *(float2*)&outp[OUT_IMG + ((size_t)(b*CIN + orow + 8))*HWSZ + col] =
                make_float2(acc3[j][2] + bb1, acc3[j][3] + bb1);
        }
    }
}

// ---------------- K5: mask + top-81 ----------------
__global__ __launch_bounds__(1024) void k_topk_mask(float* __restrict__ outp){
    __shared__ unsigned long long warr[32];
    __shared__ unsigned long long swin;
    __shared__ float sred[32];
    __shared__ float s_mn, s_mx;
    int b = blockIdx.x, t = threadIdx.x;
    int lane = t & 31, w = t >> 5;
    float v[4];
    float mn = 1e30f, mx = -1e30f;
    #pragma unroll
    for (int i = 0; i < 4; i++){
        v[i] = g_rowmax[b*HWSZ + t + (i<<10)];
        mn = fminf(mn, v[i]); mx = fmaxf(mx, v[i]);
    }
    mn = wMinF(mn);
    if (lane == 0) sred[w] = mn;
    __syncthreads();
    if (w == 0){ float x = wMinF(sred[lane]); if (lane == 0) s_mn = x; }
    __syncthreads();
    mx = wMaxF(mx);
    if (lane == 0) sred[w] = mx;
    __syncthreads();
    if (w == 0){ float x = wMaxF(sred[lane]); if (lane == 0) s_mx = x; }
    __syncthreads();
    float mn3 = s_mn*s_mn*s_mn, mx3 = s_mx*s_mx*s_mx;
    float inv = 1.f / (mx3 - mn3);
    #pragma unroll
    for (int i = 0; i < 4; i++){
        int l = t + (i<<10);
        outp[OUT_MASK + b*HWSZ + l] = 1.f - (v[i]*v[i]*v[i] - mn3) * inv;
    }
    for (int it = 0; it < KSEL; it++){
        unsigned long long best = 0ull;
        #pragma unroll
        for (int i = 0; i < 4; i++){
            int l = t + (i<<10);
            unsigned long long key =
                ((unsigned long long)__float_as_uint(v[i]) << 32) | (unsigned)(0xFFFFFFFFu - (unsigned)l);
            if (key > best) best = key;
        }
        best = wMaxU(best);
        if (lane == 0) warr[w] = best;
        __syncthreads();
        if (w == 0){
            unsigned long long x = wMaxU(warr[lane]);
            if (lane == 0){
                swin = x;
                g_topidx[b*KSEL + it] = (int)(0xFFFFFFFFu - (unsigned)(x & 0xFFFFFFFFull));
            }
        }
        __syncthreads();
        unsigned long long win = swin;
        int widx = (int)(0xFFFFFFFFu - (unsigned)(win & 0xFFFFFFFFull));
        #pragma unroll
        for (int i = 0; i < 4; i++){
            int l = t + (i<<10);
            if (l == widx) v[i] = 0.f;
        }
        __syncthreads();
    }
}

// ---------------- K7: gather result rows ----------------
__global__ __launch_bounds__(128) void k_gather(float* __restrict__ outp){
    int g = blockIdx.x;
    int b = g / (BTOT*KSEL);
    int rem = g - b*(BTOT*KSEL);
    int i = rem / KSEL, k = rem - i*KSEL;
    int src = g_topidx[i*KSEL + k];
    size_t row = (size_t)(b*HWSZ + src);
    float inv = g_rowinv[row];
    const float4* s = (const float4*)&g_simE[row*NTOK];
    float4* o = (float4*)&outp[OUT_RES + (size_t)g*NTOK];
    float4 vv = s[threadIdx.x];
    vv.x *= inv; vv.y *= inv; vv.z *= inv; vv.w *= inv;
    o[threadIdx.x] = vv;
}

// ---------------- launch ----------------
extern "C" void kernel_launch(void* const* d_in, const int* in_sizes, int n_in,
                              void* d_out, int out_size){
    const float* x   = (const float*)d_in[0];
    const float* DRp = (const float*)d_in[1];
    const float* ciw = (const float*)d_in[2];
    const float* cib = (const float*)d_in[3];
    const float* sw  = (const float*)d_in[4];
    const float* sb  = (const float*)d_in[5];
    const float* n1w = (const float*)d_in[6];
    const float* n1b = (const float*)d_in[7];
    const float* n2w = (const float*)d_in[8];
    const float* n2b = (const float*)d_in[9];
    const float* cow = (const float*)d_in[10];
    const float* cob = (const float*)d_in[11];
    float* out = (float*)d_out;

    cudaFuncSetAttribute(k_fused, cudaFuncAttributeMaxDynamicSharedMemorySize, SMEM_FUSED);

    k_prep_w2  <<<DDIM, 384>>>(sw, ciw, cib, sb);
    k_prep_wout<<<CIN*DDIM/256, 256>>>(cow);
    k_ln_dr    <<<NTOK, 128>>>(DRp, n2w, n2b);
    k_fused    <<<MROW/128, 256, SMEM_FUSED>>>(x, n1w, n1b, cob, out);
    k_topk_mask<<<BTOT, 1024>>>(out);
    k_gather   <<<BTOT*BTOT*KSEL, 128>>>(out);
}